// round 1
// baseline (speedup 1.0000x reference)
#include <cuda_runtime.h>
#include <math.h>

// Problem constants
#define BB 2
#define SS 2048
#define DD 1024
#define HH 16
#define DH 64
#define NROW (BB*SS)          // 4096
#define OUT_ELEMS ((size_t)BB*SS*DD)            // 4,194,304
#define ATTN_ELEMS ((size_t)BB*HH*SS*SS)        // 134,217,728

// Scratch (device globals — no allocation allowed)
__device__ float g_Q[NROW*DD];   // [B,H,S,64] packed as ((b*H+h)*S+s)*64+d
__device__ float g_K[NROW*DD];
__device__ float g_V[NROW*DD];
__device__ float g_M[NROW*DD];   // merged attn output [B,S,D]

// ---------------------------------------------------------------------------
// Generic 128x128x16 SGEMM with bias: C = A(MxK) @ W(KxN) + bias
// mode 0: C row-major [M,N]
// mode 1: split-head store into [B,H,S,64]
// ---------------------------------------------------------------------------
__global__ __launch_bounds__(256) void gemm_bias(
    const float* __restrict__ A, const float* __restrict__ W,
    const float* __restrict__ bias, float* __restrict__ C,
    int M, int N, int K, int mode)
{
    const int t  = threadIdx.x;
    const int tx = t & 15;
    const int ty = t >> 4;
    const int m0 = blockIdx.y * 128;
    const int n0 = blockIdx.x * 128;

    __shared__ float As[16][132];   // transposed A tile [k][m]
    __shared__ float Bs[16][128];   // B tile [k][n]

    float acc[8][8] = {};

    for (int k0 = 0; k0 < K; k0 += 16) {
        // Load A tile 128x16 (transposed into As)
        #pragma unroll
        for (int it = 0; it < 8; it++) {
            int idx = t + it * 256;       // 0..2047
            int r = idx >> 4, c = idx & 15;
            As[c][r] = A[(size_t)(m0 + r) * K + k0 + c];
        }
        // Load B tile 16x128 as float4
        #pragma unroll
        for (int it = 0; it < 2; it++) {
            int v = t + it * 256;         // 0..511
            int r = v >> 5, cc = (v & 31) * 4;
            *(float4*)&Bs[r][cc] = *(const float4*)&W[(size_t)(k0 + r) * N + n0 + cc];
        }
        __syncthreads();

        #pragma unroll
        for (int k = 0; k < 16; k++) {
            float a[8], b[8];
            *(float4*)(a)     = *(float4*)&As[k][ty * 8];
            *(float4*)(a + 4) = *(float4*)&As[k][ty * 8 + 4];
            *(float4*)(b)     = *(float4*)&Bs[k][tx * 8];
            *(float4*)(b + 4) = *(float4*)&Bs[k][tx * 8 + 4];
            #pragma unroll
            for (int i = 0; i < 8; i++)
                #pragma unroll
                for (int j = 0; j < 8; j++)
                    acc[i][j] = fmaf(a[i], b[j], acc[i][j]);
        }
        __syncthreads();
    }

    #pragma unroll
    for (int i = 0; i < 8; i++) {
        int m = m0 + ty * 8 + i;
        #pragma unroll
        for (int j = 0; j < 8; j++) {
            int n = n0 + tx * 8 + j;
            float vo = acc[i][j] + bias[n];
            if (mode == 0) {
                C[(size_t)m * N + n] = vo;
            } else {
                int b = m >> 11;          // m / 2048
                int s = m & 2047;
                int h = n >> 6;           // n / 64
                int dd = n & 63;
                C[((size_t)(b * HH + h) * SS + s) * DH + dd] = vo;
            }
        }
    }
}

// ---------------------------------------------------------------------------
// Scores: attn_raw[bh, q, k] = (Q_bh @ K_bh^T) / 8
// ---------------------------------------------------------------------------
__global__ __launch_bounds__(256) void scores_kernel(
    const float* __restrict__ Q, const float* __restrict__ Km,
    float* __restrict__ attn)
{
    const int t  = threadIdx.x;
    const int tx = t & 15;
    const int ty = t >> 4;
    const int bh = blockIdx.z;
    const int m0 = blockIdx.y * 128;
    const int n0 = blockIdx.x * 128;

    const float* Qb = Q + (size_t)bh * SS * DH;
    const float* Kb = Km + (size_t)bh * SS * DH;

    __shared__ float Qs[16][132];   // [k][m]
    __shared__ float Ks[16][132];   // [k][n]

    float acc[8][8] = {};

    #pragma unroll
    for (int k0 = 0; k0 < 64; k0 += 16) {
        #pragma unroll
        for (int it = 0; it < 8; it++) {
            int idx = t + it * 256;
            int r = idx >> 4, c = idx & 15;
            Qs[c][r] = Qb[(size_t)(m0 + r) * DH + k0 + c];
            Ks[c][r] = Kb[(size_t)(n0 + r) * DH + k0 + c];
        }
        __syncthreads();
        #pragma unroll
        for (int k = 0; k < 16; k++) {
            float a[8], b[8];
            *(float4*)(a)     = *(float4*)&Qs[k][ty * 8];
            *(float4*)(a + 4) = *(float4*)&Qs[k][ty * 8 + 4];
            *(float4*)(b)     = *(float4*)&Ks[k][tx * 8];
            *(float4*)(b + 4) = *(float4*)&Ks[k][tx * 8 + 4];
            #pragma unroll
            for (int i = 0; i < 8; i++)
                #pragma unroll
                for (int j = 0; j < 8; j++)
                    acc[i][j] = fmaf(a[i], b[j], acc[i][j]);
        }
        __syncthreads();
    }

    #pragma unroll
    for (int i = 0; i < 8; i++) {
        size_t rowbase = ((size_t)bh * SS + m0 + ty * 8 + i) * SS;
        #pragma unroll
        for (int j = 0; j < 8; j++)
            attn[rowbase + n0 + tx * 8 + j] = acc[i][j] * 0.125f;
    }
}

// ---------------------------------------------------------------------------
// Row softmax in place: one block (256 threads) per row of 2048
// ---------------------------------------------------------------------------
__global__ __launch_bounds__(256) void softmax_kernel(float* __restrict__ attn)
{
    float* p = attn + (size_t)blockIdx.x * SS;
    const int t = threadIdx.x;

    float v[8];
    float mx = -1e30f;
    #pragma unroll
    for (int i = 0; i < 8; i++) {
        v[i] = p[t + i * 256];
        mx = fmaxf(mx, v[i]);
    }

    __shared__ float redm[8];
    __shared__ float reds[8];

    #pragma unroll
    for (int o = 16; o; o >>= 1)
        mx = fmaxf(mx, __shfl_xor_sync(0xffffffffu, mx, o));
    if ((t & 31) == 0) redm[t >> 5] = mx;
    __syncthreads();
    mx = redm[0];
    #pragma unroll
    for (int i = 1; i < 8; i++) mx = fmaxf(mx, redm[i]);

    float s = 0.f;
    #pragma unroll
    for (int i = 0; i < 8; i++) {
        v[i] = __expf(v[i] - mx);
        s += v[i];
    }
    #pragma unroll
    for (int o = 16; o; o >>= 1)
        s += __shfl_xor_sync(0xffffffffu, s, o);
    if ((t & 31) == 0) reds[t >> 5] = s;
    __syncthreads();
    s = reds[0];
    #pragma unroll
    for (int i = 1; i < 8; i++) s += reds[i];

    float inv = 1.0f / s;
    #pragma unroll
    for (int i = 0; i < 8; i++)
        p[t + i * 256] = v[i] * inv;
}

// ---------------------------------------------------------------------------
// AV: merged[b, s, h*64+d] = P_bh @ V_bh
// ---------------------------------------------------------------------------
__global__ __launch_bounds__(256) void av_kernel(
    const float* __restrict__ attn, const float* __restrict__ V,
    float* __restrict__ Mo)
{
    const int t  = threadIdx.x;
    const int tx = t & 15;
    const int ty = t >> 4;
    const int bh = blockIdx.y;
    const int m0 = blockIdx.x * 128;
    const int b  = bh >> 4;
    const int h  = bh & 15;

    const float* Pb = attn + (size_t)bh * SS * SS;
    const float* Vb = V + (size_t)bh * SS * DH;

    __shared__ float Ps[32][132];   // [k][m]
    __shared__ float Vs[32][68];    // [k][n]

    float acc[8][4] = {};

    for (int k0 = 0; k0 < SS; k0 += 32) {
        #pragma unroll
        for (int it = 0; it < 16; it++) {
            int idx = t + it * 256;    // 0..4095 over 128x32 tile
            int r = idx >> 5, c = idx & 31;
            Ps[c][r] = Pb[(size_t)(m0 + r) * SS + k0 + c];
        }
        #pragma unroll
        for (int it = 0; it < 8; it++) {
            int idx = t + it * 256;    // 0..2047 over 32x64 tile
            int r = idx >> 6, c = idx & 63;
            Vs[r][c] = Vb[(size_t)(k0 + r) * DH + c];
        }
        __syncthreads();
        #pragma unroll
        for (int k = 0; k < 32; k++) {
            float a[8], bv[4];
            *(float4*)(a)     = *(float4*)&Ps[k][ty * 8];
            *(float4*)(a + 4) = *(float4*)&Ps[k][ty * 8 + 4];
            *(float4*)(bv)    = *(float4*)&Vs[k][tx * 4];
            #pragma unroll
            for (int i = 0; i < 8; i++)
                #pragma unroll
                for (int j = 0; j < 4; j++)
                    acc[i][j] = fmaf(a[i], bv[j], acc[i][j]);
        }
        __syncthreads();
    }

    #pragma unroll
    for (int i = 0; i < 8; i++) {
        size_t rowbase = ((size_t)(b * SS + m0 + ty * 8 + i)) * DD + h * 64;
        #pragma unroll
        for (int j = 0; j < 4; j++)
            Mo[rowbase + tx * 4 + j] = acc[i][j];
    }
}

// ---------------------------------------------------------------------------
extern "C" void kernel_launch(void* const* d_in, const int* in_sizes, int n_in,
                              void* d_out, int out_size)
{
    const float* q  = (const float*)d_in[0];
    const float* k  = (const float*)d_in[1];
    const float* v  = (const float*)d_in[2];
    // d_in[3] = mask (unused, faithful to reference)
    const float* Wq = (const float*)d_in[4];
    const float* bq = (const float*)d_in[5];
    const float* Wk = (const float*)d_in[6];
    const float* bk = (const float*)d_in[7];
    const float* Wv = (const float*)d_in[8];
    const float* bv = (const float*)d_in[9];
    const float* Wo = (const float*)d_in[10];
    const float* bo = (const float*)d_in[11];

    float* out_ptr  = (float*)d_out;
    float* attn_ptr = (float*)d_out + OUT_ELEMS;

    float *gQ, *gK, *gV, *gM;
    cudaGetSymbolAddress((void**)&gQ, g_Q);
    cudaGetSymbolAddress((void**)&gK, g_K);
    cudaGetSymbolAddress((void**)&gV, g_V);
    cudaGetSymbolAddress((void**)&gM, g_M);

    dim3 gp(DD / 128, NROW / 128);  // (8, 32)

    // Projections with split-head store
    gemm_bias<<<gp, 256>>>(q, Wq, bq, gQ, NROW, DD, DD, 1);
    gemm_bias<<<gp, 256>>>(k, Wk, bk, gK, NROW, DD, DD, 1);
    gemm_bias<<<gp, 256>>>(v, Wv, bv, gV, NROW, DD, DD, 1);

    // Raw scaled scores into attn output region
    dim3 gs(SS / 128, SS / 128, BB * HH);   // (16,16,32)
    scores_kernel<<<gs, 256>>>(gQ, gK, attn_ptr);

    // Row softmax in place
    softmax_kernel<<<BB * HH * SS, 256>>>(attn_ptr);

    // P @ V -> merged
    dim3 ga(SS / 128, BB * HH);             // (16,32)
    av_kernel<<<ga, 256>>>(attn_ptr, gV, gM);

    // Output projection
    gemm_bias<<<gp, 256>>>(gM, Wo, bo, out_ptr, NROW, DD, DD, 0);
}

// round 2
// speedup vs baseline: 1.1868x; 1.1868x over previous
#include <cuda_runtime.h>
#include <math.h>

#define BB 2
#define SS 2048
#define DD 1024
#define HH 16
#define DH 64
#define NROW (BB*SS)
#define OUT_ELEMS ((size_t)BB*SS*DD)

// Scratch (device globals)
__device__ float g_Q[NROW*DD];   // [bh][s][64]
__device__ float g_K[NROW*DD];
__device__ float g_V[NROW*DD];
__device__ float g_M[NROW*DD];   // merged [B,S,D]

// ---------------------------------------------------------------------------
// Double-buffered 128x128x16 SGEMM + bias. mode 0: row-major C. mode 1: split heads.
// ---------------------------------------------------------------------------
__global__ __launch_bounds__(256, 2) void gemm_bias(
    const float* __restrict__ A, const float* __restrict__ W,
    const float* __restrict__ bias, float* __restrict__ C,
    int M, int N, int K, int mode)
{
    const int t  = threadIdx.x;
    const int tx = t & 15;
    const int ty = t >> 4;
    const int m0 = blockIdx.y * 128;
    const int n0 = blockIdx.x * 128;

    __shared__ float As[2][16][132];   // [buf][k][m]
    __shared__ float Bs[2][16][128];   // [buf][k][n]

    float acc[8][8] = {};

    const int NT = K / 16;
    // A-tile load indices: 512 float4 over 128x16
    const int ar0 = t >> 2, ac0 = (t & 3) * 4;
    const int ar1 = (t + 256) >> 2, ac1 = ((t + 256) & 3) * 4;
    // B-tile: 512 float4 over 16x128
    const int br0 = t >> 5, bc0 = (t & 31) * 4;
    const int br1 = (t + 256) >> 5, bc1 = ((t + 256) & 31) * 4;

    float4 sa0, sa1, sb0, sb1;
    // preload tile 0
    sa0 = *(const float4*)&A[(size_t)(m0 + ar0) * K + ac0];
    sa1 = *(const float4*)&A[(size_t)(m0 + ar1) * K + ac1];
    sb0 = *(const float4*)&W[(size_t)(br0) * N + n0 + bc0];
    sb1 = *(const float4*)&W[(size_t)(br1) * N + n0 + bc1];
    {
        As[0][ac0+0][ar0]=sa0.x; As[0][ac0+1][ar0]=sa0.y; As[0][ac0+2][ar0]=sa0.z; As[0][ac0+3][ar0]=sa0.w;
        As[0][ac1+0][ar1]=sa1.x; As[0][ac1+1][ar1]=sa1.y; As[0][ac1+2][ar1]=sa1.z; As[0][ac1+3][ar1]=sa1.w;
        *(float4*)&Bs[0][br0][bc0] = sb0;
        *(float4*)&Bs[0][br1][bc1] = sb1;
    }
    __syncthreads();

    int buf = 0;
    for (int kt = 0; kt < NT; kt++) {
        if (kt + 1 < NT) {
            int k0 = (kt + 1) * 16;
            sa0 = *(const float4*)&A[(size_t)(m0 + ar0) * K + k0 + ac0];
            sa1 = *(const float4*)&A[(size_t)(m0 + ar1) * K + k0 + ac1];
            sb0 = *(const float4*)&W[(size_t)(k0 + br0) * N + n0 + bc0];
            sb1 = *(const float4*)&W[(size_t)(k0 + br1) * N + n0 + bc1];
        }
        #pragma unroll
        for (int k = 0; k < 16; k++) {
            float a[8], b[8];
            *(float4*)(a)     = *(float4*)&As[buf][k][ty * 8];
            *(float4*)(a + 4) = *(float4*)&As[buf][k][ty * 8 + 4];
            *(float4*)(b)     = *(float4*)&Bs[buf][k][tx * 8];
            *(float4*)(b + 4) = *(float4*)&Bs[buf][k][tx * 8 + 4];
            #pragma unroll
            for (int i = 0; i < 8; i++)
                #pragma unroll
                for (int j = 0; j < 8; j++)
                    acc[i][j] = fmaf(a[i], b[j], acc[i][j]);
        }
        if (kt + 1 < NT) {
            int nb = buf ^ 1;
            As[nb][ac0+0][ar0]=sa0.x; As[nb][ac0+1][ar0]=sa0.y; As[nb][ac0+2][ar0]=sa0.z; As[nb][ac0+3][ar0]=sa0.w;
            As[nb][ac1+0][ar1]=sa1.x; As[nb][ac1+1][ar1]=sa1.y; As[nb][ac1+2][ar1]=sa1.z; As[nb][ac1+3][ar1]=sa1.w;
            *(float4*)&Bs[nb][br0][bc0] = sb0;
            *(float4*)&Bs[nb][br1][bc1] = sb1;
            __syncthreads();
            buf = nb;
        }
    }

    #pragma unroll
    for (int i = 0; i < 8; i++) {
        int m = m0 + ty * 8 + i;
        #pragma unroll
        for (int j = 0; j < 8; j++) {
            int n = n0 + tx * 8 + j;
            float vo = acc[i][j] + bias[n];
            if (mode == 0) {
                C[(size_t)m * N + n] = vo;
            } else {
                int b = m >> 11;
                int s = m & 2047;
                int h = n >> 6;
                int dd = n & 63;
                C[((size_t)(b * HH + h) * SS + s) * DH + dd] = vo;
            }
        }
    }
}

// ---------------------------------------------------------------------------
// Fused scores + softmax + AV.
// CTA = (rowblock of 128 q-rows, bh). Two passes over 16 k-tiles of 128.
// Pass 1: S = QK^T/8, online max/sum, write exp(S - m_t) to attn, record m_t.
// Pass 2: re-read, scale by exp(m_t - M)/Z, write final P, accumulate P@V.
// ---------------------------------------------------------------------------
#define SM_QS 0
#define SM_KS 8448              // 64*132
#define SM_PS 0                 // 128*132 = 16896 (aliases Qs+Ks)
#define SM_VS 16896             // 128*68 = 8704
#define SM_MT 25600             // 16*128 = 2048
#define SM_RM 27648             // 128
#define SM_RI 27776             // 128
#define SM_TOT_FLOATS 27904     // 111616 bytes

__global__ __launch_bounds__(256, 2) void fused_attn(
    const float* __restrict__ Q, const float* __restrict__ K,
    const float* __restrict__ V, float* __restrict__ attn,
    float* __restrict__ Mo)
{
    extern __shared__ float sm[];
    float* Qs = sm + SM_QS;   // [d][row] stride 132
    float* Ks = sm + SM_KS;   // [d][col] stride 132
    float* Ps = sm + SM_PS;   // [row][col] stride 132
    float* Vs = sm + SM_VS;   // [kcol][dv] stride 68
    float* mT = sm + SM_MT;   // [kt][row]
    float* rM = sm + SM_RM;
    float* rI = sm + SM_RI;

    const int t  = threadIdx.x;
    const int tx = t & 15;
    const int ty = t >> 4;
    const int rb = blockIdx.x;
    const int bh = blockIdx.y;
    const int m0 = rb * 128;

    const float* Qb = Q + (size_t)bh * SS * DH;
    const float* Kb = K + (size_t)bh * SS * DH;
    const float* Vb = V + (size_t)bh * SS * DH;

    // Load Q rowblock [128][64] -> Qs[d][row]
    #pragma unroll
    for (int it = 0; it < 8; it++) {
        int idx = t + it * 256;
        int r = idx >> 4, dg = (idx & 15) * 4;
        float4 qv = *(const float4*)&Qb[(size_t)(m0 + r) * DH + dg];
        Qs[(dg+0)*132 + r] = qv.x; Qs[(dg+1)*132 + r] = qv.y;
        Qs[(dg+2)*132 + r] = qv.z; Qs[(dg+3)*132 + r] = qv.w;
    }

    float rm[8], rs[8];
    #pragma unroll
    for (int i = 0; i < 8; i++) { rm[i] = -1e30f; rs[i] = 0.f; }

    __syncthreads();

    // ------------------- Pass 1 -------------------
    for (int kt = 0; kt < 16; kt++) {
        if (kt) __syncthreads();
        #pragma unroll
        for (int it = 0; it < 8; it++) {
            int idx = t + it * 256;
            int c = idx >> 4, dg = (idx & 15) * 4;
            float4 kv = *(const float4*)&Kb[(size_t)(kt * 128 + c) * DH + dg];
            Ks[(dg+0)*132 + c] = kv.x; Ks[(dg+1)*132 + c] = kv.y;
            Ks[(dg+2)*132 + c] = kv.z; Ks[(dg+3)*132 + c] = kv.w;
        }
        __syncthreads();

        float acc[8][8] = {};
        #pragma unroll 8
        for (int d = 0; d < 64; d++) {
            float a[8], b[8];
            *(float4*)(a)     = *(float4*)&Qs[d*132 + ty * 8];
            *(float4*)(a + 4) = *(float4*)&Qs[d*132 + ty * 8 + 4];
            *(float4*)(b)     = *(float4*)&Ks[d*132 + tx * 8];
            *(float4*)(b + 4) = *(float4*)&Ks[d*132 + tx * 8 + 4];
            #pragma unroll
            for (int i = 0; i < 8; i++)
                #pragma unroll
                for (int j = 0; j < 8; j++)
                    acc[i][j] = fmaf(a[i], b[j], acc[i][j]);
        }

        #pragma unroll
        for (int i = 0; i < 8; i++) {
            #pragma unroll
            for (int j = 0; j < 8; j++) acc[i][j] *= 0.125f;
            float tm = acc[i][0];
            #pragma unroll
            for (int j = 1; j < 8; j++) tm = fmaxf(tm, acc[i][j]);
            #pragma unroll
            for (int o = 8; o; o >>= 1)
                tm = fmaxf(tm, __shfl_xor_sync(0xffffffffu, tm, o));
            float nm = fmaxf(rm[i], tm);
            float tsum = 0.f;
            #pragma unroll
            for (int j = 0; j < 8; j++) {
                acc[i][j] = __expf(acc[i][j] - nm);
                tsum += acc[i][j];
            }
            #pragma unroll
            for (int o = 8; o; o >>= 1)
                tsum += __shfl_xor_sync(0xffffffffu, tsum, o);
            rs[i] = rs[i] * __expf(rm[i] - nm) + tsum;
            rm[i] = nm;
            if (tx == 0) mT[kt * 128 + ty * 8 + i] = nm;
            float4* dst = (float4*)&attn[((size_t)bh * SS + m0 + ty * 8 + i) * SS
                                         + kt * 128 + tx * 8];
            dst[0] = make_float4(acc[i][0], acc[i][1], acc[i][2], acc[i][3]);
            dst[1] = make_float4(acc[i][4], acc[i][5], acc[i][6], acc[i][7]);
        }
    }

    #pragma unroll
    for (int i = 0; i < 8; i++) {
        if (tx == 0) {
            rM[ty * 8 + i] = rm[i];
            rI[ty * 8 + i] = 1.0f / rs[i];
        }
    }

    // ------------------- Pass 2 -------------------
    float acc2[8][4] = {};
    for (int kt = 0; kt < 16; kt++) {
        __syncthreads();   // previous AV reads done, Ps/Vs reusable (first iter: covers region0 reuse)
        #pragma unroll
        for (int it = 0; it < 8; it++) {
            int idx = t + it * 256;
            int r = idx >> 4, dg = (idx & 15) * 4;
            *(float4*)&Vs[r * 68 + dg] =
                *(const float4*)&Vb[(size_t)(kt * 128 + r) * DH + dg];
        }
        #pragma unroll
        for (int i = 0; i < 8; i++) {
            int row = ty * 8 + i;
            float f = __expf(mT[kt * 128 + row] - rM[row]) * rI[row];
            float4* ptr = (float4*)&attn[((size_t)bh * SS + m0 + row) * SS
                                         + kt * 128 + tx * 8];
            float4 e0 = ptr[0], e1 = ptr[1];
            e0.x *= f; e0.y *= f; e0.z *= f; e0.w *= f;
            e1.x *= f; e1.y *= f; e1.z *= f; e1.w *= f;
            ptr[0] = e0; ptr[1] = e1;
            float* pr = &Ps[row * 132 + tx * 8];
            pr[0]=e0.x; pr[1]=e0.y; pr[2]=e0.z; pr[3]=e0.w;
            pr[4]=e1.x; pr[5]=e1.y; pr[6]=e1.z; pr[7]=e1.w;
        }
        __syncthreads();

        #pragma unroll 4
        for (int c = 0; c < 128; c += 4) {
            float bv[4][4];
            *(float4*)bv[0] = *(float4*)&Vs[(c+0) * 68 + tx * 4];
            *(float4*)bv[1] = *(float4*)&Vs[(c+1) * 68 + tx * 4];
            *(float4*)bv[2] = *(float4*)&Vs[(c+2) * 68 + tx * 4];
            *(float4*)bv[3] = *(float4*)&Vs[(c+3) * 68 + tx * 4];
            #pragma unroll
            for (int i = 0; i < 8; i++) {
                float4 av = *(float4*)&Ps[(ty * 8 + i) * 132 + c];
                #pragma unroll
                for (int j = 0; j < 4; j++) {
                    acc2[i][j] = fmaf(av.x, bv[0][j], acc2[i][j]);
                    acc2[i][j] = fmaf(av.y, bv[1][j], acc2[i][j]);
                    acc2[i][j] = fmaf(av.z, bv[2][j], acc2[i][j]);
                    acc2[i][j] = fmaf(av.w, bv[3][j], acc2[i][j]);
                }
            }
        }
    }

    const int b = bh >> 4, h = bh & 15;
    #pragma unroll
    for (int i = 0; i < 8; i++) {
        size_t rowbase = ((size_t)(b * SS + m0 + ty * 8 + i)) * DD + h * 64;
        *(float4*)&Mo[rowbase + tx * 4] =
            make_float4(acc2[i][0], acc2[i][1], acc2[i][2], acc2[i][3]);
    }
}

// ---------------------------------------------------------------------------
extern "C" void kernel_launch(void* const* d_in, const int* in_sizes, int n_in,
                              void* d_out, int out_size)
{
    const float* q  = (const float*)d_in[0];
    const float* k  = (const float*)d_in[1];
    const float* v  = (const float*)d_in[2];
    const float* Wq = (const float*)d_in[4];
    const float* bq = (const float*)d_in[5];
    const float* Wk = (const float*)d_in[6];
    const float* bk = (const float*)d_in[7];
    const float* Wv = (const float*)d_in[8];
    const float* bv = (const float*)d_in[9];
    const float* Wo = (const float*)d_in[10];
    const float* bo = (const float*)d_in[11];

    float* out_ptr  = (float*)d_out;
    float* attn_ptr = (float*)d_out + OUT_ELEMS;

    float *gQ, *gK, *gV, *gM;
    cudaGetSymbolAddress((void**)&gQ, g_Q);
    cudaGetSymbolAddress((void**)&gK, g_K);
    cudaGetSymbolAddress((void**)&gV, g_V);
    cudaGetSymbolAddress((void**)&gM, g_M);

    static int smem_set = 0;
    if (!smem_set) {
        cudaFuncSetAttribute(fused_attn, cudaFuncAttributeMaxDynamicSharedMemorySize,
                             SM_TOT_FLOATS * 4);
        smem_set = 1;
    }

    dim3 gp(DD / 128, NROW / 128);  // (8, 32)
    gemm_bias<<<gp, 256>>>(q, Wq, bq, gQ, NROW, DD, DD, 1);
    gemm_bias<<<gp, 256>>>(k, Wk, bk, gK, NROW, DD, DD, 1);
    gemm_bias<<<gp, 256>>>(v, Wv, bv, gV, NROW, DD, DD, 1);

    dim3 gf(SS / 128, BB * HH);     // (16, 32)
    fused_attn<<<gf, 256, SM_TOT_FLOATS * 4>>>(gQ, gK, gV, attn_ptr, gM);

    gemm_bias<<<gp, 256>>>(gM, Wo, bo, out_ptr, NROW, DD, DD, 0);
}

// round 4
// speedup vs baseline: 1.7234x; 1.4522x over previous
#include <cuda_runtime.h>
#include <cuda_bf16.h>
#include <math.h>
#include <stdint.h>

#define BB 2
#define SS 2048
#define DD 1024
#define HH 16
#define DH 64
#define NROW (BB*SS)
#define OUT_ELEMS ((size_t)BB*SS*DD)

// Scratch (device globals)
__device__ float g_Q[NROW*DD];
__device__ float g_K[NROW*DD];
__device__ float g_V[NROW*DD];
__device__ float g_M[NROW*DD];
__device__ __nv_bfloat16 g_Ah[NROW*DD];
__device__ __nv_bfloat16 g_Al[NROW*DD];
__device__ __nv_bfloat16 g_Wh[DD*DD];
__device__ __nv_bfloat16 g_Wl[DD*DD];

// ===========================================================================
// helpers
// ===========================================================================
__device__ __forceinline__ uint32_t smem_u32(const void* p) {
    uint32_t a;
    asm("{ .reg .u64 t; cvta.to.shared.u64 t, %1; cvt.u32.u64 %0, t; }"
        : "=r"(a) : "l"(p));
    return a;
}
__device__ __forceinline__ uint32_t sw128(uint32_t off) {
    return off ^ ((off >> 3) & 0x70);
}
__device__ __forceinline__ void cp16(uint32_t dst, const void* src) {
    asm volatile("cp.async.cg.shared.global [%0], [%1], 16;"
                 :: "r"(dst), "l"(src));
}
__device__ __forceinline__ void cp_commit() {
    asm volatile("cp.async.commit_group;" ::: "memory");
}
__device__ __forceinline__ void ldsm_x4(uint32_t& r0, uint32_t& r1,
                                        uint32_t& r2, uint32_t& r3, uint32_t a) {
    asm volatile("ldmatrix.sync.aligned.m8n8.x4.shared.b16 {%0,%1,%2,%3}, [%4];"
                 : "=r"(r0), "=r"(r1), "=r"(r2), "=r"(r3) : "r"(a));
}
__device__ __forceinline__ void ldsm_x4t(uint32_t& r0, uint32_t& r1,
                                         uint32_t& r2, uint32_t& r3, uint32_t a) {
    asm volatile("ldmatrix.sync.aligned.m8n8.x4.trans.shared.b16 {%0,%1,%2,%3}, [%4];"
                 : "=r"(r0), "=r"(r1), "=r"(r2), "=r"(r3) : "r"(a));
}
__device__ __forceinline__ void mma16816(float* d, const uint32_t* a, const uint32_t* b) {
    asm volatile(
        "mma.sync.aligned.m16n8k16.row.col.f32.bf16.bf16.f32 "
        "{%0,%1,%2,%3}, {%4,%5,%6,%7}, {%8,%9}, {%0,%1,%2,%3};"
        : "+f"(d[0]), "+f"(d[1]), "+f"(d[2]), "+f"(d[3])
        : "r"(a[0]), "r"(a[1]), "r"(a[2]), "r"(a[3]), "r"(b[0]), "r"(b[1]));
}

// ===========================================================================
// fp32 -> bf16 hi/lo split (elementwise, vectorized)
// ===========================================================================
__global__ __launch_bounds__(256) void split_bf16(
    const float4* __restrict__ in, uint2* __restrict__ hi,
    uint2* __restrict__ lo, int n4)
{
    int i = blockIdx.x * 256 + threadIdx.x;
    if (i >= n4) return;
    float4 v = in[i];
    float f[4] = {v.x, v.y, v.z, v.w};
    uint16_t h[4], l[4];
    #pragma unroll
    for (int j = 0; j < 4; j++) {
        __nv_bfloat16 hb = __float2bfloat16(f[j]);
        __nv_bfloat16 lb = __float2bfloat16(f[j] - __bfloat162float(hb));
        h[j] = __bfloat16_as_ushort(hb);
        l[j] = __bfloat16_as_ushort(lb);
    }
    hi[i] = make_uint2((uint32_t)h[0] | ((uint32_t)h[1] << 16),
                       (uint32_t)h[2] | ((uint32_t)h[3] << 16));
    lo[i] = make_uint2((uint32_t)l[0] | ((uint32_t)l[1] << 16),
                       (uint32_t)l[2] | ((uint32_t)l[3] << 16));
}

// ===========================================================================
// HMMA bf16-split GEMM: C[4096x1024] = (Ah+Al)[4096x1024] @ (Bh+Bl)[1024x1024] + bias
// CTA 128x128, K-slab 64, double-buffered cp.async, 8 warps (2x4), warp 64x32.
// ===========================================================================
#define NTS 16
#define GSTAGE 65536
// in-stage offsets: Ah 0, Al 16384, B hi sub0 32768, sub1 40960, B lo 49152/57344
#define SM_GEMM_BYTES 131072

__global__ __launch_bounds__(256, 1) void gemm_hmma(
    const __nv_bfloat16* __restrict__ Agh, const __nv_bfloat16* __restrict__ Agl,
    const __nv_bfloat16* __restrict__ Wgh, const __nv_bfloat16* __restrict__ Wgl,
    const float* __restrict__ bias, float* __restrict__ C, int mode)
{
    extern __shared__ char smc[];
    const uint32_t sb = smem_u32(smc);
    const int t = threadIdx.x;
    const int lane = t & 31;
    const int wid = t >> 5;
    const int wm = wid & 1;        // 2 warps over M
    const int wn = wid >> 1;       // 4 warps over N
    const int m0 = blockIdx.y * 128;
    const int n0 = blockIdx.x * 128;

    float acc[4][4][4] = {};

    // --- prefetch stage s ---
    auto prefetch = [&](int s) {
        const int ksl = s * 64;
        const uint32_t base = sb + (s & 1) * GSTAGE;
        #pragma unroll
        for (int i = 0; i < 4; i++) {
            int idx = t + i * 256;           // 0..1023
            int row = idx >> 3, ck = idx & 7;
            uint32_t so = sw128((uint32_t)(row * 128 + ck * 16));
            size_t g = (size_t)(m0 + row) * DD + ksl + ck * 8;
            cp16(base + so, Agh + g);
            cp16(base + 16384 + so, Agl + g);
        }
        #pragma unroll
        for (int i = 0; i < 4; i++) {
            int idx = t + i * 256;           // 0..1023
            int kr = idx >> 4, cn = idx & 15;
            uint32_t so = (uint32_t)((cn >> 3) * 8192)
                        + sw128((uint32_t)(kr * 128 + (cn & 7) * 16));
            size_t g = (size_t)(ksl + kr) * DD + n0 + cn * 8;
            cp16(base + 32768 + so, Wgh + g);
            cp16(base + 49152 + so, Wgl + g);
        }
        cp_commit();
    };

    prefetch(0);
    prefetch(1);

    for (int s = 0; s < NTS; s++) {
        if (s < NTS - 1) asm volatile("cp.async.wait_group 1;" ::: "memory");
        else             asm volatile("cp.async.wait_group 0;" ::: "memory");
        __syncthreads();

        const uint32_t aB  = sb + (s & 1) * GSTAGE;
        const uint32_t alB = aB + 16384;
        const uint32_t bhB = aB + 32768;
        const uint32_t blB = aB + 49152;

        const int lg = lane >> 3, l7 = lane & 7;

        #pragma unroll
        for (int ks = 0; ks < 4; ks++) {
            const int kb = ks * 32;          // byte offset within 128B row

            // B fragments: 4 n8-frags hi + lo
            uint32_t bh[4][2], bl[4][2];
            #pragma unroll
            for (int jj = 0; jj < 2; jj++) {
                int nloc = wn * 32 + jj * 16;
                uint32_t stb = (uint32_t)((nloc >> 6) * 8192);
                int ncol = nloc & 63;
                int krow = ks * 16 + (lg & 1) * 8 + l7;
                uint32_t off = stb + sw128((uint32_t)(krow * 128 + ncol * 2 + (lg >> 1) * 16));
                uint32_t r0, r1, r2, r3;
                ldsm_x4t(r0, r1, r2, r3, bhB + off);
                bh[jj*2+0][0] = r0; bh[jj*2+0][1] = r1;
                bh[jj*2+1][0] = r2; bh[jj*2+1][1] = r3;
                ldsm_x4t(r0, r1, r2, r3, blB + off);
                bl[jj*2+0][0] = r0; bl[jj*2+0][1] = r1;
                bl[jj*2+1][0] = r2; bl[jj*2+1][1] = r3;
            }

            #pragma unroll
            for (int im = 0; im < 4; im++) {
                int arow = wm * 64 + im * 16 + (lg & 1) * 8 + l7;
                uint32_t off = sw128((uint32_t)(arow * 128 + kb + (lg >> 1) * 16));
                uint32_t ah[4], al[4];
                ldsm_x4(ah[0], ah[1], ah[2], ah[3], aB + off);
                ldsm_x4(al[0], al[1], al[2], al[3], alB + off);
                #pragma unroll
                for (int jn = 0; jn < 4; jn++) {
                    mma16816(acc[im][jn], ah, bh[jn]);
                    mma16816(acc[im][jn], ah, bl[jn]);
                    mma16816(acc[im][jn], al, bh[jn]);
                }
            }
        }

        __syncthreads();
        if (s + 2 < NTS) prefetch(s + 2);
    }

    // Epilogue
    #pragma unroll
    for (int im = 0; im < 4; im++) {
        int r0 = m0 + wm * 64 + im * 16 + (lane >> 2);
        #pragma unroll
        for (int jn = 0; jn < 4; jn++) {
            int col = n0 + wn * 32 + jn * 8 + (lane & 3) * 2;
            float b0 = bias[col], b1 = bias[col + 1];
            float2 v0 = make_float2(acc[im][jn][0] + b0, acc[im][jn][1] + b1);
            float2 v1 = make_float2(acc[im][jn][2] + b0, acc[im][jn][3] + b1);
            if (mode == 0) {
                *(float2*)&C[(size_t)r0 * DD + col] = v0;
                *(float2*)&C[(size_t)(r0 + 8) * DD + col] = v1;
            } else {
                int h = col >> 6, dd = col & 63;
                int b_ = r0 >> 11, s0 = r0 & 2047;
                int b2 = (r0 + 8) >> 11, s1 = (r0 + 8) & 2047;
                *(float2*)&C[((size_t)(b_ * HH + h) * SS + s0) * DH + dd] = v0;
                *(float2*)&C[((size_t)(b2 * HH + h) * SS + s1) * DH + dd] = v1;
            }
        }
    }
}

// ===========================================================================
// Fused scores + softmax + AV (unchanged)
// ===========================================================================
#define SM_QS 0
#define SM_KS 8448
#define SM_PS 0
#define SM_VS 16896
#define SM_MT 25600
#define SM_RM 27648
#define SM_RI 27776
#define SM_TOT_FLOATS 27904

__global__ __launch_bounds__(256, 2) void fused_attn(
    const float* __restrict__ Q, const float* __restrict__ K,
    const float* __restrict__ V, float* __restrict__ attn,
    float* __restrict__ Mo)
{
    extern __shared__ float sm[];
    float* Qs = sm + SM_QS;
    float* Ks = sm + SM_KS;
    float* Ps = sm + SM_PS;
    float* Vs = sm + SM_VS;
    float* mT = sm + SM_MT;
    float* rM = sm + SM_RM;
    float* rI = sm + SM_RI;

    const int t  = threadIdx.x;
    const int tx = t & 15;
    const int ty = t >> 4;
    const int rb = blockIdx.x;
    const int bh = blockIdx.y;
    const int m0 = rb * 128;

    const float* Qb = Q + (size_t)bh * SS * DH;
    const float* Kb = K + (size_t)bh * SS * DH;
    const float* Vb = V + (size_t)bh * SS * DH;

    #pragma unroll
    for (int it = 0; it < 8; it++) {
        int idx = t + it * 256;
        int r = idx >> 4, dg = (idx & 15) * 4;
        float4 qv = *(const float4*)&Qb[(size_t)(m0 + r) * DH + dg];
        Qs[(dg+0)*132 + r] = qv.x; Qs[(dg+1)*132 + r] = qv.y;
        Qs[(dg+2)*132 + r] = qv.z; Qs[(dg+3)*132 + r] = qv.w;
    }

    float rm[8], rs[8];
    #pragma unroll
    for (int i = 0; i < 8; i++) { rm[i] = -1e30f; rs[i] = 0.f; }

    __syncthreads();

    for (int kt = 0; kt < 16; kt++) {
        if (kt) __syncthreads();
        #pragma unroll
        for (int it = 0; it < 8; it++) {
            int idx = t + it * 256;
            int c = idx >> 4, dg = (idx & 15) * 4;
            float4 kv = *(const float4*)&Kb[(size_t)(kt * 128 + c) * DH + dg];
            Ks[(dg+0)*132 + c] = kv.x; Ks[(dg+1)*132 + c] = kv.y;
            Ks[(dg+2)*132 + c] = kv.z; Ks[(dg+3)*132 + c] = kv.w;
        }
        __syncthreads();

        float acc[8][8] = {};
        #pragma unroll 8
        for (int d = 0; d < 64; d++) {
            float a[8], b[8];
            *(float4*)(a)     = *(float4*)&Qs[d*132 + ty * 8];
            *(float4*)(a + 4) = *(float4*)&Qs[d*132 + ty * 8 + 4];
            *(float4*)(b)     = *(float4*)&Ks[d*132 + tx * 8];
            *(float4*)(b + 4) = *(float4*)&Ks[d*132 + tx * 8 + 4];
            #pragma unroll
            for (int i = 0; i < 8; i++)
                #pragma unroll
                for (int j = 0; j < 8; j++)
                    acc[i][j] = fmaf(a[i], b[j], acc[i][j]);
        }

        #pragma unroll
        for (int i = 0; i < 8; i++) {
            #pragma unroll
            for (int j = 0; j < 8; j++) acc[i][j] *= 0.125f;
            float tm = acc[i][0];
            #pragma unroll
            for (int j = 1; j < 8; j++) tm = fmaxf(tm, acc[i][j]);
            #pragma unroll
            for (int o = 8; o; o >>= 1)
                tm = fmaxf(tm, __shfl_xor_sync(0xffffffffu, tm, o));
            float nm = fmaxf(rm[i], tm);
            float tsum = 0.f;
            #pragma unroll
            for (int j = 0; j < 8; j++) {
                acc[i][j] = __expf(acc[i][j] - nm);
                tsum += acc[i][j];
            }
            #pragma unroll
            for (int o = 8; o; o >>= 1)
                tsum += __shfl_xor_sync(0xffffffffu, tsum, o);
            rs[i] = rs[i] * __expf(rm[i] - nm) + tsum;
            rm[i] = nm;
            if (tx == 0) mT[kt * 128 + ty * 8 + i] = nm;
            float4* dst = (float4*)&attn[((size_t)bh * SS + m0 + ty * 8 + i) * SS
                                         + kt * 128 + tx * 8];
            dst[0] = make_float4(acc[i][0], acc[i][1], acc[i][2], acc[i][3]);
            dst[1] = make_float4(acc[i][4], acc[i][5], acc[i][6], acc[i][7]);
        }
    }

    #pragma unroll
    for (int i = 0; i < 8; i++) {
        if (tx == 0) {
            rM[ty * 8 + i] = rm[i];
            rI[ty * 8 + i] = 1.0f / rs[i];
        }
    }

    float acc2[8][4] = {};
    for (int kt = 0; kt < 16; kt++) {
        __syncthreads();
        #pragma unroll
        for (int it = 0; it < 8; it++) {
            int idx = t + it * 256;
            int r = idx >> 4, dg = (idx & 15) * 4;
            *(float4*)&Vs[r * 68 + dg] =
                *(const float4*)&Vb[(size_t)(kt * 128 + r) * DH + dg];
        }
        #pragma unroll
        for (int i = 0; i < 8; i++) {
            int row = ty * 8 + i;
            float f = __expf(mT[kt * 128 + row] - rM[row]) * rI[row];
            float4* ptr = (float4*)&attn[((size_t)bh * SS + m0 + row) * SS
                                         + kt * 128 + tx * 8];
            float4 e0 = ptr[0], e1 = ptr[1];
            e0.x *= f; e0.y *= f; e0.z *= f; e0.w *= f;
            e1.x *= f; e1.y *= f; e1.z *= f; e1.w *= f;
            ptr[0] = e0; ptr[1] = e1;
            float* pr = &Ps[row * 132 + tx * 8];
            pr[0]=e0.x; pr[1]=e0.y; pr[2]=e0.z; pr[3]=e0.w;
            pr[4]=e1.x; pr[5]=e1.y; pr[6]=e1.z; pr[7]=e1.w;
        }
        __syncthreads();

        #pragma unroll 4
        for (int c = 0; c < 128; c += 4) {
            float bv[4][4];
            *(float4*)bv[0] = *(float4*)&Vs[(c+0) * 68 + tx * 4];
            *(float4*)bv[1] = *(float4*)&Vs[(c+1) * 68 + tx * 4];
            *(float4*)bv[2] = *(float4*)&Vs[(c+2) * 68 + tx * 4];
            *(float4*)bv[3] = *(float4*)&Vs[(c+3) * 68 + tx * 4];
            #pragma unroll
            for (int i = 0; i < 8; i++) {
                float4 av = *(float4*)&Ps[(ty * 8 + i) * 132 + c];
                #pragma unroll
                for (int j = 0; j < 4; j++) {
                    acc2[i][j] = fmaf(av.x, bv[0][j], acc2[i][j]);
                    acc2[i][j] = fmaf(av.y, bv[1][j], acc2[i][j]);
                    acc2[i][j] = fmaf(av.z, bv[2][j], acc2[i][j]);
                    acc2[i][j] = fmaf(av.w, bv[3][j], acc2[i][j]);
                }
            }
        }
    }

    const int b = bh >> 4, h = bh & 15;
    #pragma unroll
    for (int i = 0; i < 8; i++) {
        size_t rowbase = ((size_t)(b * SS + m0 + ty * 8 + i)) * DD + h * 64;
        *(float4*)&Mo[rowbase + tx * 4] =
            make_float4(acc2[i][0], acc2[i][1], acc2[i][2], acc2[i][3]);
    }
}

// ===========================================================================
extern "C" void kernel_launch(void* const* d_in, const int* in_sizes, int n_in,
                              void* d_out, int out_size)
{
    const float* q  = (const float*)d_in[0];
    const float* k  = (const float*)d_in[1];
    const float* v  = (const float*)d_in[2];
    const float* Wq = (const float*)d_in[4];
    const float* bq = (const float*)d_in[5];
    const float* Wk = (const float*)d_in[6];
    const float* bk = (const float*)d_in[7];
    const float* Wv = (const float*)d_in[8];
    const float* bv = (const float*)d_in[9];
    const float* Wo = (const float*)d_in[10];
    const float* bo = (const float*)d_in[11];

    float* out_ptr  = (float*)d_out;
    float* attn_ptr = (float*)d_out + OUT_ELEMS;

    float *gQ, *gK, *gV, *gM;
    __nv_bfloat16 *gAh, *gAl, *gWh, *gWl;
    cudaGetSymbolAddress((void**)&gQ, g_Q);
    cudaGetSymbolAddress((void**)&gK, g_K);
    cudaGetSymbolAddress((void**)&gV, g_V);
    cudaGetSymbolAddress((void**)&gM, g_M);
    cudaGetSymbolAddress((void**)&gAh, g_Ah);
    cudaGetSymbolAddress((void**)&gAl, g_Al);
    cudaGetSymbolAddress((void**)&gWh, g_Wh);
    cudaGetSymbolAddress((void**)&gWl, g_Wl);

    cudaFuncSetAttribute(gemm_hmma, cudaFuncAttributeMaxDynamicSharedMemorySize,
                         SM_GEMM_BYTES);
    cudaFuncSetAttribute(fused_attn, cudaFuncAttributeMaxDynamicSharedMemorySize,
                         SM_TOT_FLOATS * 4);

    const int NA4 = (int)(OUT_ELEMS / 4);     // 1M float4 per activation
    const int NW4 = DD * DD / 4;              // 256K float4 per weight
    dim3 gp(DD / 128, NROW / 128);            // (8, 32)

    // Q projection
    split_bf16<<<(NA4 + 255) / 256, 256>>>((const float4*)q, (uint2*)gAh, (uint2*)gAl, NA4);
    split_bf16<<<(NW4 + 255) / 256, 256>>>((const float4*)Wq, (uint2*)gWh, (uint2*)gWl, NW4);
    gemm_hmma<<<gp, 256, SM_GEMM_BYTES>>>(gAh, gAl, gWh, gWl, bq, gQ, 1);
    // K projection
    split_bf16<<<(NA4 + 255) / 256, 256>>>((const float4*)k, (uint2*)gAh, (uint2*)gAl, NA4);
    split_bf16<<<(NW4 + 255) / 256, 256>>>((const float4*)Wk, (uint2*)gWh, (uint2*)gWl, NW4);
    gemm_hmma<<<gp, 256, SM_GEMM_BYTES>>>(gAh, gAl, gWh, gWl, bk, gK, 1);
    // V projection
    split_bf16<<<(NA4 + 255) / 256, 256>>>((const float4*)v, (uint2*)gAh, (uint2*)gAl, NA4);
    split_bf16<<<(NW4 + 255) / 256, 256>>>((const float4*)Wv, (uint2*)gWh, (uint2*)gWl, NW4);
    gemm_hmma<<<gp, 256, SM_GEMM_BYTES>>>(gAh, gAl, gWh, gWl, bv, gV, 1);

    // Attention (fp32 SIMT, unchanged)
    dim3 gf(SS / 128, BB * HH);
    fused_attn<<<gf, 256, SM_TOT_FLOATS * 4>>>(gQ, gK, gV, attn_ptr, gM);

    // Output projection
    split_bf16<<<(NA4 + 255) / 256, 256>>>((const float4*)gM, (uint2*)gAh, (uint2*)gAl, NA4);
    split_bf16<<<(NW4 + 255) / 256, 256>>>((const float4*)Wo, (uint2*)gWh, (uint2*)gWl, NW4);
    gemm_hmma<<<gp, 256, SM_GEMM_BYTES>>>(gAh, gAl, gWh, gWl, bo, out_ptr, 0);
}

// round 5
// speedup vs baseline: 2.9918x; 1.7360x over previous
#include <cuda_runtime.h>
#include <cuda_bf16.h>
#include <math.h>
#include <stdint.h>

#define BB 2
#define SS 2048
#define DD 1024
#define HH 16
#define DH 64
#define NROW (BB*SS)
#define OUT_ELEMS ((size_t)BB*SS*DD)

// Scratch (device globals)
__device__ float g_M[NROW*DD];                 // merged attn output [B,S,D]
__device__ __nv_bfloat16 g_Ah[NROW*DD];        // activation split for gemm
__device__ __nv_bfloat16 g_Al[NROW*DD];
__device__ __nv_bfloat16 g_Wh[DD*DD];
__device__ __nv_bfloat16 g_Wl[DD*DD];
__device__ __nv_bfloat16 g_Qh[NROW*DD];        // [bh][s][64] bf16 hi/lo
__device__ __nv_bfloat16 g_Ql[NROW*DD];
__device__ __nv_bfloat16 g_Kh[NROW*DD];
__device__ __nv_bfloat16 g_Kl[NROW*DD];
__device__ __nv_bfloat16 g_Vh[NROW*DD];
__device__ __nv_bfloat16 g_Vl[NROW*DD];

// ===========================================================================
// helpers
// ===========================================================================
__device__ __forceinline__ uint32_t smem_u32(const void* p) {
    uint32_t a;
    asm("{ .reg .u64 t; cvta.to.shared.u64 t, %1; cvt.u32.u64 %0, t; }"
        : "=r"(a) : "l"(p));
    return a;
}
__device__ __forceinline__ uint32_t sw128(uint32_t off) {
    return off ^ ((off >> 3) & 0x70);
}
__device__ __forceinline__ void cp16(uint32_t dst, const void* src) {
    asm volatile("cp.async.cg.shared.global [%0], [%1], 16;"
                 :: "r"(dst), "l"(src));
}
__device__ __forceinline__ void cp_commit() {
    asm volatile("cp.async.commit_group;" ::: "memory");
}
__device__ __forceinline__ void ldsm_x4(uint32_t& r0, uint32_t& r1,
                                        uint32_t& r2, uint32_t& r3, uint32_t a) {
    asm volatile("ldmatrix.sync.aligned.m8n8.x4.shared.b16 {%0,%1,%2,%3}, [%4];"
                 : "=r"(r0), "=r"(r1), "=r"(r2), "=r"(r3) : "r"(a));
}
__device__ __forceinline__ void ldsm_x4t(uint32_t& r0, uint32_t& r1,
                                         uint32_t& r2, uint32_t& r3, uint32_t a) {
    asm volatile("ldmatrix.sync.aligned.m8n8.x4.trans.shared.b16 {%0,%1,%2,%3}, [%4];"
                 : "=r"(r0), "=r"(r1), "=r"(r2), "=r"(r3) : "r"(a));
}
__device__ __forceinline__ void mma16816(float* d, const uint32_t* a, const uint32_t* b) {
    asm volatile(
        "mma.sync.aligned.m16n8k16.row.col.f32.bf16.bf16.f32 "
        "{%0,%1,%2,%3}, {%4,%5,%6,%7}, {%8,%9}, {%0,%1,%2,%3};"
        : "+f"(d[0]), "+f"(d[1]), "+f"(d[2]), "+f"(d[3])
        : "r"(a[0]), "r"(a[1]), "r"(a[2]), "r"(a[3]), "r"(b[0]), "r"(b[1]));
}
// pack two fp32 -> bf16x2 (lo = first arg)
__device__ __forceinline__ uint32_t pack_bf16x2(float lo, float hi) {
    uint32_t r;
    asm("cvt.rn.bf16x2.f32 %0, %1, %2;" : "=r"(r) : "f"(hi), "f"(lo));
    return r;
}

// ===========================================================================
// fp32 -> bf16 hi/lo split (elementwise)
// ===========================================================================
__global__ __launch_bounds__(256) void split_bf16(
    const float4* __restrict__ in, uint2* __restrict__ hi,
    uint2* __restrict__ lo, int n4)
{
    int i = blockIdx.x * 256 + threadIdx.x;
    if (i >= n4) return;
    float4 v = in[i];
    float f[4] = {v.x, v.y, v.z, v.w};
    uint16_t h[4], l[4];
    #pragma unroll
    for (int j = 0; j < 4; j++) {
        __nv_bfloat16 hb = __float2bfloat16(f[j]);
        __nv_bfloat16 lb = __float2bfloat16(f[j] - __bfloat162float(hb));
        h[j] = __bfloat16_as_ushort(hb);
        l[j] = __bfloat16_as_ushort(lb);
    }
    hi[i] = make_uint2((uint32_t)h[0] | ((uint32_t)h[1] << 16),
                       (uint32_t)h[2] | ((uint32_t)h[3] << 16));
    lo[i] = make_uint2((uint32_t)l[0] | ((uint32_t)l[1] << 16),
                       (uint32_t)l[2] | ((uint32_t)l[3] << 16));
}

// ===========================================================================
// HMMA bf16-split GEMM.
// mode 0: fp32 row-major store (C).
// mode 2: bf16 hi/lo split-head store (Ch/Cl), values scaled by `scale`.
// ===========================================================================
#define NTS 16
#define GSTAGE 65536
#define SM_GEMM_BYTES 131072

__global__ __launch_bounds__(256, 1) void gemm_hmma(
    const __nv_bfloat16* __restrict__ Agh, const __nv_bfloat16* __restrict__ Agl,
    const __nv_bfloat16* __restrict__ Wgh, const __nv_bfloat16* __restrict__ Wgl,
    const float* __restrict__ bias, float* __restrict__ C,
    __nv_bfloat16* __restrict__ Ch, __nv_bfloat16* __restrict__ Cl,
    float scale, int mode)
{
    extern __shared__ char smc[];
    const uint32_t sb = smem_u32(smc);
    const int t = threadIdx.x;
    const int lane = t & 31;
    const int wid = t >> 5;
    const int wm = wid & 1;
    const int wn = wid >> 1;
    const int m0 = blockIdx.y * 128;
    const int n0 = blockIdx.x * 128;

    float acc[4][4][4] = {};

    auto prefetch = [&](int s) {
        const int ksl = s * 64;
        const uint32_t base = sb + (s & 1) * GSTAGE;
        #pragma unroll
        for (int i = 0; i < 4; i++) {
            int idx = t + i * 256;
            int row = idx >> 3, ck = idx & 7;
            uint32_t so = sw128((uint32_t)(row * 128 + ck * 16));
            size_t g = (size_t)(m0 + row) * DD + ksl + ck * 8;
            cp16(base + so, Agh + g);
            cp16(base + 16384 + so, Agl + g);
        }
        #pragma unroll
        for (int i = 0; i < 4; i++) {
            int idx = t + i * 256;
            int kr = idx >> 4, cn = idx & 15;
            uint32_t so = (uint32_t)((cn >> 3) * 8192)
                        + sw128((uint32_t)(kr * 128 + (cn & 7) * 16));
            size_t g = (size_t)(ksl + kr) * DD + n0 + cn * 8;
            cp16(base + 32768 + so, Wgh + g);
            cp16(base + 49152 + so, Wgl + g);
        }
        cp_commit();
    };

    prefetch(0);
    prefetch(1);

    for (int s = 0; s < NTS; s++) {
        if (s < NTS - 1) asm volatile("cp.async.wait_group 1;" ::: "memory");
        else             asm volatile("cp.async.wait_group 0;" ::: "memory");
        __syncthreads();

        const uint32_t aB  = sb + (s & 1) * GSTAGE;
        const uint32_t alB = aB + 16384;
        const uint32_t bhB = aB + 32768;
        const uint32_t blB = aB + 49152;

        const int lg = lane >> 3, l7 = lane & 7;

        #pragma unroll
        for (int ks = 0; ks < 4; ks++) {
            const int kb = ks * 32;
            uint32_t bh[4][2], bl[4][2];
            #pragma unroll
            for (int jj = 0; jj < 2; jj++) {
                int nloc = wn * 32 + jj * 16;
                uint32_t stb = (uint32_t)((nloc >> 6) * 8192);
                int ncol = nloc & 63;
                int krow = ks * 16 + (lg & 1) * 8 + l7;
                uint32_t off = stb + sw128((uint32_t)(krow * 128 + ncol * 2 + (lg >> 1) * 16));
                uint32_t r0, r1, r2, r3;
                ldsm_x4t(r0, r1, r2, r3, bhB + off);
                bh[jj*2+0][0] = r0; bh[jj*2+0][1] = r1;
                bh[jj*2+1][0] = r2; bh[jj*2+1][1] = r3;
                ldsm_x4t(r0, r1, r2, r3, blB + off);
                bl[jj*2+0][0] = r0; bl[jj*2+0][1] = r1;
                bl[jj*2+1][0] = r2; bl[jj*2+1][1] = r3;
            }
            #pragma unroll
            for (int im = 0; im < 4; im++) {
                int arow = wm * 64 + im * 16 + (lg & 1) * 8 + l7;
                uint32_t off = sw128((uint32_t)(arow * 128 + kb + (lg >> 1) * 16));
                uint32_t ah[4], al[4];
                ldsm_x4(ah[0], ah[1], ah[2], ah[3], aB + off);
                ldsm_x4(al[0], al[1], al[2], al[3], alB + off);
                #pragma unroll
                for (int jn = 0; jn < 4; jn++) {
                    mma16816(acc[im][jn], ah, bh[jn]);
                    mma16816(acc[im][jn], ah, bl[jn]);
                    mma16816(acc[im][jn], al, bh[jn]);
                }
            }
        }
        __syncthreads();
        if (s + 2 < NTS) prefetch(s + 2);
    }

    #pragma unroll
    for (int im = 0; im < 4; im++) {
        int r0 = m0 + wm * 64 + im * 16 + (lane >> 2);
        #pragma unroll
        for (int jn = 0; jn < 4; jn++) {
            int col = n0 + wn * 32 + jn * 8 + (lane & 3) * 2;
            float b0 = bias[col], b1 = bias[col + 1];
            float v00 = acc[im][jn][0] + b0, v01 = acc[im][jn][1] + b1;
            float v10 = acc[im][jn][2] + b0, v11 = acc[im][jn][3] + b1;
            if (mode == 0) {
                *(float2*)&C[(size_t)r0 * DD + col] = make_float2(v00, v01);
                *(float2*)&C[(size_t)(r0 + 8) * DD + col] = make_float2(v10, v11);
            } else {
                v00 *= scale; v01 *= scale; v10 *= scale; v11 *= scale;
                int h = col >> 6, dd = col & 63;
                int b_ = r0 >> 11, s0 = r0 & 2047;
                int b2 = (r0 + 8) >> 11, s1 = (r0 + 8) & 2047;
                size_t off0 = ((size_t)(b_ * HH + h) * SS + s0) * DH + dd;
                size_t off1 = ((size_t)(b2 * HH + h) * SS + s1) * DH + dd;
                uint32_t p0 = pack_bf16x2(v00, v01);
                uint32_t p1 = pack_bf16x2(v10, v11);
                *(uint32_t*)&Ch[off0] = p0;
                *(uint32_t*)&Ch[off1] = p1;
                uint32_t q0 = pack_bf16x2(v00 - __uint_as_float(p0 << 16),
                                          v01 - __uint_as_float(p0 & 0xffff0000u));
                uint32_t q1 = pack_bf16x2(v10 - __uint_as_float(p1 << 16),
                                          v11 - __uint_as_float(p1 & 0xffff0000u));
                *(uint32_t*)&Cl[off0] = q0;
                *(uint32_t*)&Cl[off1] = q1;
            }
        }
    }
}

// ===========================================================================
// Fused attention v2 (HMMA). Two passes over K tiles:
//  A: S = QK^T (split HMMA), rowsum += exp(S)
//  B: recompute S, p = exp(S)/Z -> store attn, O += P@V (split HMMA)
// Q pre-scaled by 0.125 in projection epilogue.
// ===========================================================================
#define FA_SMEM 163840  // Q 32K + 2 stages x 64K (Kh,Kl,Vh,Vl)

__global__ __launch_bounds__(256, 1) void fused_attn2(
    const __nv_bfloat16* __restrict__ Qh, const __nv_bfloat16* __restrict__ Ql,
    const __nv_bfloat16* __restrict__ Kh, const __nv_bfloat16* __restrict__ Kl,
    const __nv_bfloat16* __restrict__ Vh, const __nv_bfloat16* __restrict__ Vl,
    float* __restrict__ attn, float* __restrict__ Mo)
{
    extern __shared__ char smc[];
    const uint32_t sb = smem_u32(smc);
    const int t = threadIdx.x, lane = t & 31, wid = t >> 5;
    const int m0 = blockIdx.x * 128, bh = blockIdx.y;
    const int mw = wid * 16;
    const size_t gB = (size_t)bh * SS * DH;

    const uint32_t sQh = sb, sQl = sb + 16384;

    // lane-derived ldsm address components
    const int rA  = mw + (lane & 15);
    const int cA  = (lane & 16);
    const int rBn = (lane & 7) + ((lane & 16) >> 1);
    const int cB  = ((lane & 8) << 1);
    const int rV  = (lane & 7) + (lane & 8);
    const int cV  = (lane >> 4) * 16;

    // ---- Q loads (committed with first K prefetch) ----
    #pragma unroll
    for (int i = 0; i < 4; i++) {
        int idx = t + i * 256;
        int row = idx >> 3, ck = idx & 7;
        uint32_t so = sw128((uint32_t)(row * 128 + ck * 16));
        size_t g = gB + (size_t)(m0 + row) * DH + ck * 8;
        cp16(sQh + so, Qh + g);
        cp16(sQl + so, Ql + g);
    }

    auto prefK = [&](int kt) {
        uint32_t base = sb + 32768 + (uint32_t)(kt & 1) * 65536;
        #pragma unroll
        for (int i = 0; i < 4; i++) {
            int idx = t + i * 256;
            int row = idx >> 3, ck = idx & 7;
            uint32_t so = sw128((uint32_t)(row * 128 + ck * 16));
            size_t g = gB + (size_t)(kt * 128 + row) * DH + ck * 8;
            cp16(base + so, Kh + g);
            cp16(base + 16384 + so, Kl + g);
        }
        cp_commit();
    };
    auto prefKV = [&](int kt) {
        uint32_t base = sb + 32768 + (uint32_t)(kt & 1) * 65536;
        #pragma unroll
        for (int i = 0; i < 4; i++) {
            int idx = t + i * 256;
            int row = idx >> 3, ck = idx & 7;
            uint32_t so = sw128((uint32_t)(row * 128 + ck * 16));
            size_t g = gB + (size_t)(kt * 128 + row) * DH + ck * 8;
            cp16(base + so, Kh + g);
            cp16(base + 16384 + so, Kl + g);
            cp16(base + 32768 + so, Vh + g);
            cp16(base + 49152 + so, Vl + g);
        }
        cp_commit();
    };

    // computes S tile (128 wide) for this warp into acc[16][4]
    auto computeS = [&](uint32_t kb, float (*acc)[4]) {
        #pragma unroll
        for (int kg = 0; kg < 4; kg++) {
            uint32_t offA = sw128((uint32_t)(rA * 128 + kg * 32 + cA));
            uint32_t ah[4], al[4];
            ldsm_x4(ah[0], ah[1], ah[2], ah[3], sQh + offA);
            ldsm_x4(al[0], al[1], al[2], al[3], sQl + offA);
            #pragma unroll
            for (int j = 0; j < 8; j++) {
                uint32_t offB = sw128((uint32_t)((j * 16 + rBn) * 128 + kg * 32 + cB));
                uint32_t b0, b1, b2, b3, c0, c1, c2, c3;
                ldsm_x4(b0, b1, b2, b3, kb + offB);
                ldsm_x4(c0, c1, c2, c3, kb + 16384 + offB);
                uint32_t bh0[2] = {b0, b1}, bh1[2] = {b2, b3};
                uint32_t bl0[2] = {c0, c1}, bl1[2] = {c2, c3};
                mma16816(acc[2*j],   ah, bh0);
                mma16816(acc[2*j],   al, bh0);
                mma16816(acc[2*j],   ah, bl0);
                mma16816(acc[2*j+1], ah, bh1);
                mma16816(acc[2*j+1], al, bh1);
                mma16816(acc[2*j+1], ah, bl1);
            }
        }
    };

    prefK(0);
    prefK(1);

    // ------------------- Pass A: rowsums -------------------
    float sum0 = 0.f, sum1 = 0.f;
    for (int kt = 0; kt < 16; kt++) {
        if (kt < 15) asm volatile("cp.async.wait_group 1;" ::: "memory");
        else         asm volatile("cp.async.wait_group 0;" ::: "memory");
        __syncthreads();
        uint32_t kb = sb + 32768 + (uint32_t)(kt & 1) * 65536;

        float acc[16][4] = {};
        computeS(kb, acc);

        #pragma unroll
        for (int nt = 0; nt < 16; nt++) {
            sum0 += __expf(acc[nt][0]) + __expf(acc[nt][1]);
            sum1 += __expf(acc[nt][2]) + __expf(acc[nt][3]);
        }
        __syncthreads();
        if (kt + 2 < 16) prefK(kt + 2);
    }

    sum0 += __shfl_xor_sync(0xffffffffu, sum0, 1);
    sum0 += __shfl_xor_sync(0xffffffffu, sum0, 2);
    sum1 += __shfl_xor_sync(0xffffffffu, sum1, 1);
    sum1 += __shfl_xor_sync(0xffffffffu, sum1, 2);
    const float invZ0 = 1.0f / sum0;
    const float invZ1 = 1.0f / sum1;

    __syncthreads();
    prefKV(0);
    prefKV(1);

    // ------------------- Pass B: write P, accumulate O -------------------
    float o[8][4] = {};
    const size_t arow0 = (size_t)bh * SS + m0 + mw + (lane >> 2);
    const size_t arow8 = arow0 + 8;

    for (int kt = 0; kt < 16; kt++) {
        if (kt < 15) asm volatile("cp.async.wait_group 1;" ::: "memory");
        else         asm volatile("cp.async.wait_group 0;" ::: "memory");
        __syncthreads();
        uint32_t kb = sb + 32768 + (uint32_t)(kt & 1) * 65536;

        float acc[16][4] = {};
        computeS(kb, acc);

        #pragma unroll
        for (int nt = 0; nt < 16; nt++) {
            float p0 = __expf(acc[nt][0]) * invZ0;
            float p1 = __expf(acc[nt][1]) * invZ0;
            float p2 = __expf(acc[nt][2]) * invZ1;
            float p3 = __expf(acc[nt][3]) * invZ1;
            acc[nt][0] = p0; acc[nt][1] = p1; acc[nt][2] = p2; acc[nt][3] = p3;
            int col = kt * 128 + nt * 8 + (lane & 3) * 2;
            *(float2*)&attn[arow0 * SS + col] = make_float2(p0, p1);
            *(float2*)&attn[arow8 * SS + col] = make_float2(p2, p3);
        }

        #pragma unroll
        for (int kg = 0; kg < 8; kg++) {
            // A fragments for P from S registers (ntiles 2kg, 2kg+1)
            uint32_t ph[4], pl[4];
            #pragma unroll
            for (int half = 0; half < 2; half++) {
                float* a4 = acc[2*kg + half];
                uint32_t h0 = pack_bf16x2(a4[0], a4[1]);
                uint32_t h1 = pack_bf16x2(a4[2], a4[3]);
                ph[half*2 + 0] = h0;   // wait: order below
                ph[half*2 + 1] = h1;
                pl[half*2 + 0] = pack_bf16x2(a4[0] - __uint_as_float(h0 << 16),
                                             a4[1] - __uint_as_float(h0 & 0xffff0000u));
                pl[half*2 + 1] = pack_bf16x2(a4[2] - __uint_as_float(h1 << 16),
                                             a4[3] - __uint_as_float(h1 & 0xffff0000u));
            }
            // a-frag order: a0=(r,k0) a1=(r+8,k0) a2=(r,k8) a3=(r+8,k8)
            // half 0 (ntile 2kg)   -> k0..7 : h0=(r), h1=(r+8)  => ph[0],ph[1]
            // half 1 (ntile 2kg+1) -> k8..15: h0=(r), h1=(r+8)  => ph[2],ph[3]
            #pragma unroll
            for (int j = 0; j < 4; j++) {
                uint32_t offV = sw128((uint32_t)((kg * 16 + rV) * 128 + j * 32 + cV));
                uint32_t v0, v1, v2, v3, w0, w1, w2, w3;
                ldsm_x4t(v0, v1, v2, v3, kb + 32768 + offV);
                ldsm_x4t(w0, w1, w2, w3, kb + 49152 + offV);
                uint32_t vh0[2] = {v0, v1}, vh1[2] = {v2, v3};
                uint32_t vl0[2] = {w0, w1}, vl1[2] = {w2, w3};
                mma16816(o[2*j],   ph, vh0);
                mma16816(o[2*j],   pl, vh0);
                mma16816(o[2*j],   ph, vl0);
                mma16816(o[2*j+1], ph, vh1);
                mma16816(o[2*j+1], pl, vh1);
                mma16816(o[2*j+1], ph, vl1);
            }
        }
        __syncthreads();
        if (kt + 2 < 16) prefKV(kt + 2);
    }

    // ---- store O to merged layout ----
    const int b = bh >> 4, h = bh & 15;
    const size_t mrow0 = (size_t)(b * SS + m0 + mw + (lane >> 2));
    #pragma unroll
    for (int nt = 0; nt < 8; nt++) {
        int col = h * 64 + nt * 8 + (lane & 3) * 2;
        *(float2*)&Mo[mrow0 * DD + col]       = make_float2(o[nt][0], o[nt][1]);
        *(float2*)&Mo[(mrow0 + 8) * DD + col] = make_float2(o[nt][2], o[nt][3]);
    }
}

// ===========================================================================
extern "C" void kernel_launch(void* const* d_in, const int* in_sizes, int n_in,
                              void* d_out, int out_size)
{
    const float* q  = (const float*)d_in[0];
    const float* k  = (const float*)d_in[1];
    const float* v  = (const float*)d_in[2];
    const float* Wq = (const float*)d_in[4];
    const float* bq = (const float*)d_in[5];
    const float* Wk = (const float*)d_in[6];
    const float* bk = (const float*)d_in[7];
    const float* Wv = (const float*)d_in[8];
    const float* bv = (const float*)d_in[9];
    const float* Wo = (const float*)d_in[10];
    const float* bo = (const float*)d_in[11];

    float* out_ptr  = (float*)d_out;
    float* attn_ptr = (float*)d_out + OUT_ELEMS;

    float* gM;
    __nv_bfloat16 *gAh, *gAl, *gWh, *gWl, *gQh, *gQl, *gKh, *gKl, *gVh, *gVl;
    cudaGetSymbolAddress((void**)&gM, g_M);
    cudaGetSymbolAddress((void**)&gAh, g_Ah);
    cudaGetSymbolAddress((void**)&gAl, g_Al);
    cudaGetSymbolAddress((void**)&gWh, g_Wh);
    cudaGetSymbolAddress((void**)&gWl, g_Wl);
    cudaGetSymbolAddress((void**)&gQh, g_Qh);
    cudaGetSymbolAddress((void**)&gQl, g_Ql);
    cudaGetSymbolAddress((void**)&gKh, g_Kh);
    cudaGetSymbolAddress((void**)&gKl, g_Kl);
    cudaGetSymbolAddress((void**)&gVh, g_Vh);
    cudaGetSymbolAddress((void**)&gVl, g_Vl);

    cudaFuncSetAttribute(gemm_hmma, cudaFuncAttributeMaxDynamicSharedMemorySize,
                         SM_GEMM_BYTES);
    cudaFuncSetAttribute(fused_attn2, cudaFuncAttributeMaxDynamicSharedMemorySize,
                         FA_SMEM);

    const int NA4 = (int)(OUT_ELEMS / 4);
    const int NW4 = DD * DD / 4;
    dim3 gp(DD / 128, NROW / 128);   // (8, 32)

    // Q projection (scaled by 1/8, bf16-split split-head output)
    split_bf16<<<(NA4 + 255) / 256, 256>>>((const float4*)q, (uint2*)gAh, (uint2*)gAl, NA4);
    split_bf16<<<(NW4 + 255) / 256, 256>>>((const float4*)Wq, (uint2*)gWh, (uint2*)gWl, NW4);
    gemm_hmma<<<gp, 256, SM_GEMM_BYTES>>>(gAh, gAl, gWh, gWl, bq, nullptr, gQh, gQl, 0.125f, 2);
    // K projection
    split_bf16<<<(NA4 + 255) / 256, 256>>>((const float4*)k, (uint2*)gAh, (uint2*)gAl, NA4);
    split_bf16<<<(NW4 + 255) / 256, 256>>>((const float4*)Wk, (uint2*)gWh, (uint2*)gWl, NW4);
    gemm_hmma<<<gp, 256, SM_GEMM_BYTES>>>(gAh, gAl, gWh, gWl, bk, nullptr, gKh, gKl, 1.0f, 2);
    // V projection
    split_bf16<<<(NA4 + 255) / 256, 256>>>((const float4*)v, (uint2*)gAh, (uint2*)gAl, NA4);
    split_bf16<<<(NW4 + 255) / 256, 256>>>((const float4*)Wv, (uint2*)gWh, (uint2*)gWl, NW4);
    gemm_hmma<<<gp, 256, SM_GEMM_BYTES>>>(gAh, gAl, gWh, gWl, bv, nullptr, gVh, gVl, 1.0f, 2);

    // Fused attention (HMMA)
    dim3 gf(SS / 128, BB * HH);      // (16, 32)
    fused_attn2<<<gf, 256, FA_SMEM>>>(gQh, gQl, gKh, gKl, gVh, gVl, attn_ptr, gM);

    // Output projection (fp32 store)
    split_bf16<<<(NA4 + 255) / 256, 256>>>((const float4*)gM, (uint2*)gAh, (uint2*)gAl, NA4);
    split_bf16<<<(NW4 + 255) / 256, 256>>>((const float4*)Wo, (uint2*)gWh, (uint2*)gWl, NW4);
    gemm_hmma<<<gp, 256, SM_GEMM_BYTES>>>(gAh, gAl, gWh, gWl, bo, out_ptr, nullptr, nullptr, 1.0f, 0);
}

// round 7
// speedup vs baseline: 3.3049x; 1.1046x over previous
#include <cuda_runtime.h>
#include <cuda_bf16.h>
#include <math.h>
#include <stdint.h>

#define BB 2
#define SS 2048
#define DD 1024
#define HH 16
#define DH 64
#define NROW (BB*SS)
#define OUT_ELEMS ((size_t)BB*SS*DD)

// Scratch (device globals)
__device__ float g_M[NROW*DD];                 // merged attn output [B,S,D]
__device__ __nv_bfloat16 g_Ah[NROW*DD];        // gM split (output proj)
__device__ __nv_bfloat16 g_Al[NROW*DD];
// input activation splits
__device__ __nv_bfloat16 g_Sqh[NROW*DD], g_Sql[NROW*DD];
__device__ __nv_bfloat16 g_Skh[NROW*DD], g_Skl[NROW*DD];
__device__ __nv_bfloat16 g_Svh[NROW*DD], g_Svl[NROW*DD];
// weight splits
__device__ __nv_bfloat16 g_W1h[DD*DD], g_W1l[DD*DD];
__device__ __nv_bfloat16 g_W2h[DD*DD], g_W2l[DD*DD];
__device__ __nv_bfloat16 g_W3h[DD*DD], g_W3l[DD*DD];
__device__ __nv_bfloat16 g_W4h[DD*DD], g_W4l[DD*DD];
// projected Q/K/V split-head bf16 hi/lo
__device__ __nv_bfloat16 g_Qh[NROW*DD], g_Ql[NROW*DD];
__device__ __nv_bfloat16 g_Kh[NROW*DD], g_Kl[NROW*DD];
__device__ __nv_bfloat16 g_Vh[NROW*DD], g_Vl[NROW*DD];

// ===========================================================================
// helpers
// ===========================================================================
__device__ __forceinline__ float fast_exp2(float x) {
    float r;
    asm("ex2.approx.f32 %0, %1;" : "=f"(r) : "f"(x));
    return r;
}
__device__ __forceinline__ uint32_t smem_u32(const void* p) {
    uint32_t a;
    asm("{ .reg .u64 t; cvta.to.shared.u64 t, %1; cvt.u32.u64 %0, t; }"
        : "=r"(a) : "l"(p));
    return a;
}
__device__ __forceinline__ uint32_t sw128(uint32_t off) {
    return off ^ ((off >> 3) & 0x70);
}
__device__ __forceinline__ void cp16(uint32_t dst, const void* src) {
    asm volatile("cp.async.cg.shared.global [%0], [%1], 16;"
                 :: "r"(dst), "l"(src));
}
__device__ __forceinline__ void cp_commit() {
    asm volatile("cp.async.commit_group;" ::: "memory");
}
__device__ __forceinline__ void ldsm_x4(uint32_t& r0, uint32_t& r1,
                                        uint32_t& r2, uint32_t& r3, uint32_t a) {
    asm volatile("ldmatrix.sync.aligned.m8n8.x4.shared.b16 {%0,%1,%2,%3}, [%4];"
                 : "=r"(r0), "=r"(r1), "=r"(r2), "=r"(r3) : "r"(a));
}
__device__ __forceinline__ void ldsm_x4t(uint32_t& r0, uint32_t& r1,
                                         uint32_t& r2, uint32_t& r3, uint32_t a) {
    asm volatile("ldmatrix.sync.aligned.m8n8.x4.trans.shared.b16 {%0,%1,%2,%3}, [%4];"
                 : "=r"(r0), "=r"(r1), "=r"(r2), "=r"(r3) : "r"(a));
}
__device__ __forceinline__ void mma16816(float* d, const uint32_t* a, const uint32_t* b) {
    asm volatile(
        "mma.sync.aligned.m16n8k16.row.col.f32.bf16.bf16.f32 "
        "{%0,%1,%2,%3}, {%4,%5,%6,%7}, {%8,%9}, {%0,%1,%2,%3};"
        : "+f"(d[0]), "+f"(d[1]), "+f"(d[2]), "+f"(d[3])
        : "r"(a[0]), "r"(a[1]), "r"(a[2]), "r"(a[3]), "r"(b[0]), "r"(b[1]));
}
__device__ __forceinline__ uint32_t pack_bf16x2(float lo, float hi) {
    uint32_t r;
    asm("cvt.rn.bf16x2.f32 %0, %1, %2;" : "=r"(r) : "f"(hi), "f"(lo));
    return r;
}

// ===========================================================================
// batched fp32 -> bf16 hi/lo split
// ===========================================================================
struct SplitJob { const float4* in; uint2* hi; uint2* lo; int n4; };
struct SplitJobs { SplitJob j[7]; };

__device__ __forceinline__ void do_split(const float4* in, uint2* hi, uint2* lo, int i) {
    float4 v = in[i];
    float f[4] = {v.x, v.y, v.z, v.w};
    uint16_t h[4], l[4];
    #pragma unroll
    for (int j = 0; j < 4; j++) {
        __nv_bfloat16 hb = __float2bfloat16(f[j]);
        __nv_bfloat16 lb = __float2bfloat16(f[j] - __bfloat162float(hb));
        h[j] = __bfloat16_as_ushort(hb);
        l[j] = __bfloat16_as_ushort(lb);
    }
    hi[i] = make_uint2((uint32_t)h[0] | ((uint32_t)h[1] << 16),
                       (uint32_t)h[2] | ((uint32_t)h[3] << 16));
    lo[i] = make_uint2((uint32_t)l[0] | ((uint32_t)l[1] << 16),
                       (uint32_t)l[2] | ((uint32_t)l[3] << 16));
}

__global__ __launch_bounds__(256) void split_batch(SplitJobs jobs) {
    SplitJob jb = jobs.j[blockIdx.y];
    int i = blockIdx.x * 256 + threadIdx.x;
    if (i >= jb.n4) return;
    do_split(jb.in, jb.hi, jb.lo, i);
}

__global__ __launch_bounds__(256) void split_bf16(
    const float4* __restrict__ in, uint2* __restrict__ hi,
    uint2* __restrict__ lo, int n4)
{
    int i = blockIdx.x * 256 + threadIdx.x;
    if (i >= n4) return;
    do_split(in, hi, lo, i);
}

// ===========================================================================
// HMMA bf16-split GEMM
// ===========================================================================
#define NTS 16
#define GSTAGE 65536
#define SM_GEMM_BYTES 131072

__global__ __launch_bounds__(256, 1) void gemm_hmma(
    const __nv_bfloat16* __restrict__ Agh, const __nv_bfloat16* __restrict__ Agl,
    const __nv_bfloat16* __restrict__ Wgh, const __nv_bfloat16* __restrict__ Wgl,
    const float* __restrict__ bias, float* __restrict__ C,
    __nv_bfloat16* __restrict__ Ch, __nv_bfloat16* __restrict__ Cl,
    float scale, int mode)
{
    extern __shared__ char smc[];
    const uint32_t sb = smem_u32(smc);
    const int t = threadIdx.x;
    const int lane = t & 31;
    const int wid = t >> 5;
    const int wm = wid & 1;
    const int wn = wid >> 1;
    const int m0 = blockIdx.y * 128;
    const int n0 = blockIdx.x * 128;

    float acc[4][4][4] = {};

    auto prefetch = [&](int s) {
        const int ksl = s * 64;
        const uint32_t base = sb + (s & 1) * GSTAGE;
        #pragma unroll
        for (int i = 0; i < 4; i++) {
            int idx = t + i * 256;
            int row = idx >> 3, ck = idx & 7;
            uint32_t so = sw128((uint32_t)(row * 128 + ck * 16));
            size_t g = (size_t)(m0 + row) * DD + ksl + ck * 8;
            cp16(base + so, Agh + g);
            cp16(base + 16384 + so, Agl + g);
        }
        #pragma unroll
        for (int i = 0; i < 4; i++) {
            int idx = t + i * 256;
            int kr = idx >> 4, cn = idx & 15;
            uint32_t so = (uint32_t)((cn >> 3) * 8192)
                        + sw128((uint32_t)(kr * 128 + (cn & 7) * 16));
            size_t g = (size_t)(ksl + kr) * DD + n0 + cn * 8;
            cp16(base + 32768 + so, Wgh + g);
            cp16(base + 49152 + so, Wgl + g);
        }
        cp_commit();
    };

    prefetch(0);
    prefetch(1);

    for (int s = 0; s < NTS; s++) {
        if (s < NTS - 1) asm volatile("cp.async.wait_group 1;" ::: "memory");
        else             asm volatile("cp.async.wait_group 0;" ::: "memory");
        __syncthreads();

        const uint32_t aB  = sb + (s & 1) * GSTAGE;
        const uint32_t alB = aB + 16384;
        const uint32_t bhB = aB + 32768;
        const uint32_t blB = aB + 49152;

        const int lg = lane >> 3, l7 = lane & 7;

        #pragma unroll
        for (int ks = 0; ks < 4; ks++) {
            const int kb = ks * 32;
            uint32_t bh[4][2], bl[4][2];
            #pragma unroll
            for (int jj = 0; jj < 2; jj++) {
                int nloc = wn * 32 + jj * 16;
                uint32_t stb = (uint32_t)((nloc >> 6) * 8192);
                int ncol = nloc & 63;
                int krow = ks * 16 + (lg & 1) * 8 + l7;
                uint32_t off = stb + sw128((uint32_t)(krow * 128 + ncol * 2 + (lg >> 1) * 16));
                uint32_t r0, r1, r2, r3;
                ldsm_x4t(r0, r1, r2, r3, bhB + off);
                bh[jj*2+0][0] = r0; bh[jj*2+0][1] = r1;
                bh[jj*2+1][0] = r2; bh[jj*2+1][1] = r3;
                ldsm_x4t(r0, r1, r2, r3, blB + off);
                bl[jj*2+0][0] = r0; bl[jj*2+0][1] = r1;
                bl[jj*2+1][0] = r2; bl[jj*2+1][1] = r3;
            }
            #pragma unroll
            for (int im = 0; im < 4; im++) {
                int arow = wm * 64 + im * 16 + (lg & 1) * 8 + l7;
                uint32_t off = sw128((uint32_t)(arow * 128 + kb + (lg >> 1) * 16));
                uint32_t ah[4], al[4];
                ldsm_x4(ah[0], ah[1], ah[2], ah[3], aB + off);
                ldsm_x4(al[0], al[1], al[2], al[3], alB + off);
                #pragma unroll
                for (int jn = 0; jn < 4; jn++) {
                    mma16816(acc[im][jn], ah, bh[jn]);
                    mma16816(acc[im][jn], ah, bl[jn]);
                    mma16816(acc[im][jn], al, bh[jn]);
                }
            }
        }
        __syncthreads();
        if (s + 2 < NTS) prefetch(s + 2);
    }

    #pragma unroll
    for (int im = 0; im < 4; im++) {
        int r0 = m0 + wm * 64 + im * 16 + (lane >> 2);
        #pragma unroll
        for (int jn = 0; jn < 4; jn++) {
            int col = n0 + wn * 32 + jn * 8 + (lane & 3) * 2;
            float b0 = bias[col], b1 = bias[col + 1];
            float v00 = acc[im][jn][0] + b0, v01 = acc[im][jn][1] + b1;
            float v10 = acc[im][jn][2] + b0, v11 = acc[im][jn][3] + b1;
            if (mode == 0) {
                *(float2*)&C[(size_t)r0 * DD + col] = make_float2(v00, v01);
                *(float2*)&C[(size_t)(r0 + 8) * DD + col] = make_float2(v10, v11);
            } else {
                v00 *= scale; v01 *= scale; v10 *= scale; v11 *= scale;
                int h = col >> 6, dd = col & 63;
                int b_ = r0 >> 11, s0 = r0 & 2047;
                int b2 = (r0 + 8) >> 11, s1 = (r0 + 8) & 2047;
                size_t off0 = ((size_t)(b_ * HH + h) * SS + s0) * DH + dd;
                size_t off1 = ((size_t)(b2 * HH + h) * SS + s1) * DH + dd;
                uint32_t p0 = pack_bf16x2(v00, v01);
                uint32_t p1 = pack_bf16x2(v10, v11);
                *(uint32_t*)&Ch[off0] = p0;
                *(uint32_t*)&Ch[off1] = p1;
                uint32_t q0 = pack_bf16x2(v00 - __uint_as_float(p0 << 16),
                                          v01 - __uint_as_float(p0 & 0xffff0000u));
                uint32_t q1 = pack_bf16x2(v10 - __uint_as_float(p1 << 16),
                                          v11 - __uint_as_float(p1 & 0xffff0000u));
                *(uint32_t*)&Cl[off0] = q0;
                *(uint32_t*)&Cl[off1] = q1;
            }
        }
    }
}

// ===========================================================================
// Fused attention v3 (HMMA).
//  Pass A: single-product QhKh -> rowsum of exp2(S~)  (Z approx, ~1e-4 rel)
//  Pass B: 3-product S, p = exp2(S)/Z -> store attn, O += P@V (3-product)
// Q pre-scaled by 0.125*log2(e) in projection epilogue.
// ===========================================================================
#define FA_SMEM 163840

__global__ __launch_bounds__(256, 1) void fused_attn2(
    const __nv_bfloat16* __restrict__ Qh, const __nv_bfloat16* __restrict__ Ql,
    const __nv_bfloat16* __restrict__ Kh, const __nv_bfloat16* __restrict__ Kl,
    const __nv_bfloat16* __restrict__ Vh, const __nv_bfloat16* __restrict__ Vl,
    float* __restrict__ attn, float* __restrict__ Mo)
{
    extern __shared__ char smc[];
    const uint32_t sb = smem_u32(smc);
    const int t = threadIdx.x, lane = t & 31, wid = t >> 5;
    const int m0 = blockIdx.x * 128, bh = blockIdx.y;
    const int mw = wid * 16;
    const size_t gB = (size_t)bh * SS * DH;

    const uint32_t sQh = sb, sQl = sb + 16384;

    const int rA  = mw + (lane & 15);
    const int cA  = (lane & 16);
    const int rBn = (lane & 7) + ((lane & 16) >> 1);
    const int cB  = ((lane & 8) << 1);
    const int rV  = (lane & 7) + (lane & 8);
    const int cV  = (lane >> 4) * 16;

    // Q loads
    #pragma unroll
    for (int i = 0; i < 4; i++) {
        int idx = t + i * 256;
        int row = idx >> 3, ck = idx & 7;
        uint32_t so = sw128((uint32_t)(row * 128 + ck * 16));
        size_t g = gB + (size_t)(m0 + row) * DH + ck * 8;
        cp16(sQh + so, Qh + g);
        cp16(sQl + so, Ql + g);
    }

    auto prefKh = [&](int kt) {
        uint32_t base = sb + 32768 + (uint32_t)(kt & 1) * 65536;
        #pragma unroll
        for (int i = 0; i < 4; i++) {
            int idx = t + i * 256;
            int row = idx >> 3, ck = idx & 7;
            uint32_t so = sw128((uint32_t)(row * 128 + ck * 16));
            cp16(base + so, Kh + gB + (size_t)(kt * 128 + row) * DH + ck * 8);
        }
        cp_commit();
    };
    auto prefKV = [&](int kt) {
        uint32_t base = sb + 32768 + (uint32_t)(kt & 1) * 65536;
        #pragma unroll
        for (int i = 0; i < 4; i++) {
            int idx = t + i * 256;
            int row = idx >> 3, ck = idx & 7;
            uint32_t so = sw128((uint32_t)(row * 128 + ck * 16));
            size_t g = gB + (size_t)(kt * 128 + row) * DH + ck * 8;
            cp16(base + so, Kh + g);
            cp16(base + 16384 + so, Kl + g);
            cp16(base + 32768 + so, Vh + g);
            cp16(base + 49152 + so, Vl + g);
        }
        cp_commit();
    };

    auto computeS1 = [&](uint32_t kb, float (*acc)[4]) {
        #pragma unroll
        for (int kg = 0; kg < 4; kg++) {
            uint32_t offA = sw128((uint32_t)(rA * 128 + kg * 32 + cA));
            uint32_t ah[4];
            ldsm_x4(ah[0], ah[1], ah[2], ah[3], sQh + offA);
            #pragma unroll
            for (int j = 0; j < 8; j++) {
                uint32_t offB = sw128((uint32_t)((j * 16 + rBn) * 128 + kg * 32 + cB));
                uint32_t b0, b1, b2, b3;
                ldsm_x4(b0, b1, b2, b3, kb + offB);
                uint32_t bh0[2] = {b0, b1}, bh1[2] = {b2, b3};
                mma16816(acc[2*j],   ah, bh0);
                mma16816(acc[2*j+1], ah, bh1);
            }
        }
    };
    auto computeS3 = [&](uint32_t kb, float (*acc)[4]) {
        #pragma unroll
        for (int kg = 0; kg < 4; kg++) {
            uint32_t offA = sw128((uint32_t)(rA * 128 + kg * 32 + cA));
            uint32_t ah[4], al[4];
            ldsm_x4(ah[0], ah[1], ah[2], ah[3], sQh + offA);
            ldsm_x4(al[0], al[1], al[2], al[3], sQl + offA);
            #pragma unroll
            for (int j = 0; j < 8; j++) {
                uint32_t offB = sw128((uint32_t)((j * 16 + rBn) * 128 + kg * 32 + cB));
                uint32_t b0, b1, b2, b3, c0, c1, c2, c3;
                ldsm_x4(b0, b1, b2, b3, kb + offB);
                ldsm_x4(c0, c1, c2, c3, kb + 16384 + offB);
                uint32_t bh0[2] = {b0, b1}, bh1[2] = {b2, b3};
                uint32_t bl0[2] = {c0, c1}, bl1[2] = {c2, c3};
                mma16816(acc[2*j],   ah, bh0);
                mma16816(acc[2*j],   al, bh0);
                mma16816(acc[2*j],   ah, bl0);
                mma16816(acc[2*j+1], ah, bh1);
                mma16816(acc[2*j+1], al, bh1);
                mma16816(acc[2*j+1], ah, bl1);
            }
        }
    };

    prefKh(0);
    prefKh(1);

    // ------------------- Pass A -------------------
    float sum0 = 0.f, sum1 = 0.f;
    for (int kt = 0; kt < 16; kt++) {
        if (kt < 15) asm volatile("cp.async.wait_group 1;" ::: "memory");
        else         asm volatile("cp.async.wait_group 0;" ::: "memory");
        __syncthreads();
        uint32_t kb = sb + 32768 + (uint32_t)(kt & 1) * 65536;

        float acc[16][4] = {};
        computeS1(kb, acc);

        #pragma unroll
        for (int nt = 0; nt < 16; nt++) {
            sum0 += fast_exp2(acc[nt][0]) + fast_exp2(acc[nt][1]);
            sum1 += fast_exp2(acc[nt][2]) + fast_exp2(acc[nt][3]);
        }
        __syncthreads();
        if (kt + 2 < 16) prefKh(kt + 2);
    }

    sum0 += __shfl_xor_sync(0xffffffffu, sum0, 1);
    sum0 += __shfl_xor_sync(0xffffffffu, sum0, 2);
    sum1 += __shfl_xor_sync(0xffffffffu, sum1, 1);
    sum1 += __shfl_xor_sync(0xffffffffu, sum1, 2);
    const float invZ0 = 1.0f / sum0;
    const float invZ1 = 1.0f / sum1;

    __syncthreads();
    prefKV(0);
    prefKV(1);

    // ------------------- Pass B -------------------
    float o[8][4] = {};
    const size_t arow0 = (size_t)bh * SS + m0 + mw + (lane >> 2);
    const size_t arow8 = arow0 + 8;

    for (int kt = 0; kt < 16; kt++) {
        if (kt < 15) asm volatile("cp.async.wait_group 1;" ::: "memory");
        else         asm volatile("cp.async.wait_group 0;" ::: "memory");
        __syncthreads();
        uint32_t kb = sb + 32768 + (uint32_t)(kt & 1) * 65536;

        float acc[16][4] = {};
        computeS3(kb, acc);

        #pragma unroll
        for (int nt = 0; nt < 16; nt++) {
            float p0 = fast_exp2(acc[nt][0]) * invZ0;
            float p1 = fast_exp2(acc[nt][1]) * invZ0;
            float p2 = fast_exp2(acc[nt][2]) * invZ1;
            float p3 = fast_exp2(acc[nt][3]) * invZ1;
            acc[nt][0] = p0; acc[nt][1] = p1; acc[nt][2] = p2; acc[nt][3] = p3;
            int col = kt * 128 + nt * 8 + (lane & 3) * 2;
            *(float2*)&attn[arow0 * SS + col] = make_float2(p0, p1);
            *(float2*)&attn[arow8 * SS + col] = make_float2(p2, p3);
        }

        #pragma unroll
        for (int kg = 0; kg < 8; kg++) {
            uint32_t ph[4], pl[4];
            #pragma unroll
            for (int half = 0; half < 2; half++) {
                float* a4 = acc[2*kg + half];
                uint32_t h0 = pack_bf16x2(a4[0], a4[1]);
                uint32_t h1 = pack_bf16x2(a4[2], a4[3]);
                ph[half*2 + 0] = h0;
                ph[half*2 + 1] = h1;
                pl[half*2 + 0] = pack_bf16x2(a4[0] - __uint_as_float(h0 << 16),
                                             a4[1] - __uint_as_float(h0 & 0xffff0000u));
                pl[half*2 + 1] = pack_bf16x2(a4[2] - __uint_as_float(h1 << 16),
                                             a4[3] - __uint_as_float(h1 & 0xffff0000u));
            }
            #pragma unroll
            for (int j = 0; j < 4; j++) {
                uint32_t offV = sw128((uint32_t)((kg * 16 + rV) * 128 + j * 32 + cV));
                uint32_t v0, v1, v2, v3, w0, w1, w2, w3;
                ldsm_x4t(v0, v1, v2, v3, kb + 32768 + offV);
                ldsm_x4t(w0, w1, w2, w3, kb + 49152 + offV);
                uint32_t vh0[2] = {v0, v1}, vh1[2] = {v2, v3};
                uint32_t vl0[2] = {w0, w1}, vl1[2] = {w2, w3};
                mma16816(o[2*j],   ph, vh0);
                mma16816(o[2*j],   pl, vh0);
                mma16816(o[2*j],   ph, vl0);
                mma16816(o[2*j+1], ph, vh1);
                mma16816(o[2*j+1], pl, vh1);
                mma16816(o[2*j+1], ph, vl1);
            }
        }
        __syncthreads();
        if (kt + 2 < 16) prefKV(kt + 2);
    }

    const int b = bh >> 4, h = bh & 15;
    const size_t mrow0 = (size_t)(b * SS + m0 + mw + (lane >> 2));
    #pragma unroll
    for (int nt = 0; nt < 8; nt++) {
        int col = h * 64 + nt * 8 + (lane & 3) * 2;
        *(float2*)&Mo[mrow0 * DD + col]       = make_float2(o[nt][0], o[nt][1]);
        *(float2*)&Mo[(mrow0 + 8) * DD + col] = make_float2(o[nt][2], o[nt][3]);
    }
}

// ===========================================================================
extern "C" void kernel_launch(void* const* d_in, const int* in_sizes, int n_in,
                              void* d_out, int out_size)
{
    const float* q  = (const float*)d_in[0];
    const float* k  = (const float*)d_in[1];
    const float* v  = (const float*)d_in[2];
    const float* Wq = (const float*)d_in[4];
    const float* bq = (const float*)d_in[5];
    const float* Wk = (const float*)d_in[6];
    const float* bk = (const float*)d_in[7];
    const float* Wv = (const float*)d_in[8];
    const float* bv = (const float*)d_in[9];
    const float* Wo = (const float*)d_in[10];
    const float* bo = (const float*)d_in[11];

    float* out_ptr  = (float*)d_out;
    float* attn_ptr = (float*)d_out + OUT_ELEMS;

    float* gM;
    __nv_bfloat16 *gAh, *gAl;
    __nv_bfloat16 *gSqh, *gSql, *gSkh, *gSkl, *gSvh, *gSvl;
    __nv_bfloat16 *gW1h, *gW1l, *gW2h, *gW2l, *gW3h, *gW3l, *gW4h, *gW4l;
    __nv_bfloat16 *gQh, *gQl, *gKh, *gKl, *gVh, *gVl;
    cudaGetSymbolAddress((void**)&gM, g_M);
    cudaGetSymbolAddress((void**)&gAh, g_Ah);
    cudaGetSymbolAddress((void**)&gAl, g_Al);
    cudaGetSymbolAddress((void**)&gSqh, g_Sqh); cudaGetSymbolAddress((void**)&gSql, g_Sql);
    cudaGetSymbolAddress((void**)&gSkh, g_Skh); cudaGetSymbolAddress((void**)&gSkl, g_Skl);
    cudaGetSymbolAddress((void**)&gSvh, g_Svh); cudaGetSymbolAddress((void**)&gSvl, g_Svl);
    cudaGetSymbolAddress((void**)&gW1h, g_W1h); cudaGetSymbolAddress((void**)&gW1l, g_W1l);
    cudaGetSymbolAddress((void**)&gW2h, g_W2h); cudaGetSymbolAddress((void**)&gW2l, g_W2l);
    cudaGetSymbolAddress((void**)&gW3h, g_W3h); cudaGetSymbolAddress((void**)&gW3l, g_W3l);
    cudaGetSymbolAddress((void**)&gW4h, g_W4h); cudaGetSymbolAddress((void**)&gW4l, g_W4l);
    cudaGetSymbolAddress((void**)&gQh, g_Qh); cudaGetSymbolAddress((void**)&gQl, g_Ql);
    cudaGetSymbolAddress((void**)&gKh, g_Kh); cudaGetSymbolAddress((void**)&gKl, g_Kl);
    cudaGetSymbolAddress((void**)&gVh, g_Vh); cudaGetSymbolAddress((void**)&gVl, g_Vl);

    cudaFuncSetAttribute(gemm_hmma, cudaFuncAttributeMaxDynamicSharedMemorySize,
                         SM_GEMM_BYTES);
    cudaFuncSetAttribute(fused_attn2, cudaFuncAttributeMaxDynamicSharedMemorySize,
                         FA_SMEM);

    const int NA4 = (int)(OUT_ELEMS / 4);
    const int NW4 = DD * DD / 4;
    dim3 gp(DD / 128, NROW / 128);

    // Batched splits: q, k, v, Wq, Wk, Wv, Wo
    SplitJobs jobs;
    jobs.j[0] = { (const float4*)q,  (uint2*)gSqh, (uint2*)gSql, NA4 };
    jobs.j[1] = { (const float4*)k,  (uint2*)gSkh, (uint2*)gSkl, NA4 };
    jobs.j[2] = { (const float4*)v,  (uint2*)gSvh, (uint2*)gSvl, NA4 };
    jobs.j[3] = { (const float4*)Wq, (uint2*)gW1h, (uint2*)gW1l, NW4 };
    jobs.j[4] = { (const float4*)Wk, (uint2*)gW2h, (uint2*)gW2l, NW4 };
    jobs.j[5] = { (const float4*)Wv, (uint2*)gW3h, (uint2*)gW3l, NW4 };
    jobs.j[6] = { (const float4*)Wo, (uint2*)gW4h, (uint2*)gW4l, NW4 };
    split_batch<<<dim3((NA4 + 255) / 256, 7), 256>>>(jobs);

    // Projections (Q scaled by 0.125*log2e)
    const float QSCALE = 0.125f * 1.4426950408889634f;
    gemm_hmma<<<gp, 256, SM_GEMM_BYTES>>>(gSqh, gSql, gW1h, gW1l, bq, nullptr, gQh, gQl, QSCALE, 2);
    gemm_hmma<<<gp, 256, SM_GEMM_BYTES>>>(gSkh, gSkl, gW2h, gW2l, bk, nullptr, gKh, gKl, 1.0f, 2);
    gemm_hmma<<<gp, 256, SM_GEMM_BYTES>>>(gSvh, gSvl, gW3h, gW3l, bv, nullptr, gVh, gVl, 1.0f, 2);

    // Fused attention
    dim3 gf(SS / 128, BB * HH);
    fused_attn2<<<gf, 256, FA_SMEM>>>(gQh, gQl, gKh, gKl, gVh, gVl, attn_ptr, gM);

    // Output projection
    split_bf16<<<(NA4 + 255) / 256, 256>>>((const float4*)gM, (uint2*)gAh, (uint2*)gAl, NA4);
    gemm_hmma<<<gp, 256, SM_GEMM_BYTES>>>(gAh, gAl, gW4h, gW4l, bo, out_ptr, nullptr, nullptr, 1.0f, 0);
}

// round 9
// speedup vs baseline: 3.3528x; 1.0145x over previous
#include <cuda_runtime.h>
#include <cuda_bf16.h>
#include <math.h>
#include <stdint.h>

#define BB 2
#define SS 2048
#define DD 1024
#define HH 16
#define DH 64
#define NROW (BB*SS)
#define OUT_ELEMS ((size_t)BB*SS*DD)

// Scratch (device globals)
__device__ __nv_bfloat16 g_Ah[NROW*DD];        // attn-out split (for out proj)
__device__ __nv_bfloat16 g_Al[NROW*DD];
// input activation splits
__device__ __nv_bfloat16 g_Sqh[NROW*DD], g_Sql[NROW*DD];
__device__ __nv_bfloat16 g_Skh[NROW*DD], g_Skl[NROW*DD];
__device__ __nv_bfloat16 g_Svh[NROW*DD], g_Svl[NROW*DD];
// weight splits
__device__ __nv_bfloat16 g_W1h[DD*DD], g_W1l[DD*DD];
__device__ __nv_bfloat16 g_W2h[DD*DD], g_W2l[DD*DD];
__device__ __nv_bfloat16 g_W3h[DD*DD], g_W3l[DD*DD];
__device__ __nv_bfloat16 g_W4h[DD*DD], g_W4l[DD*DD];
// projected Q/K/V split-head bf16 hi/lo
__device__ __nv_bfloat16 g_Qh[NROW*DD], g_Ql[NROW*DD];
__device__ __nv_bfloat16 g_Kh[NROW*DD], g_Kl[NROW*DD];
__device__ __nv_bfloat16 g_Vh[NROW*DD], g_Vl[NROW*DD];

// ===========================================================================
// helpers
// ===========================================================================
__device__ __forceinline__ float fast_exp2(float x) {
    float r;
    asm("ex2.approx.f32 %0, %1;" : "=f"(r) : "f"(x));
    return r;
}
__device__ __forceinline__ uint32_t smem_u32(const void* p) {
    uint32_t a;
    asm("{ .reg .u64 t; cvta.to.shared.u64 t, %1; cvt.u32.u64 %0, t; }"
        : "=r"(a) : "l"(p));
    return a;
}
__device__ __forceinline__ uint32_t sw128(uint32_t off) {
    return off ^ ((off >> 3) & 0x70);
}
__device__ __forceinline__ void cp16(uint32_t dst, const void* src) {
    asm volatile("cp.async.cg.shared.global [%0], [%1], 16;"
                 :: "r"(dst), "l"(src));
}
__device__ __forceinline__ void cp_commit() {
    asm volatile("cp.async.commit_group;" ::: "memory");
}
__device__ __forceinline__ void ldsm_x4(uint32_t& r0, uint32_t& r1,
                                        uint32_t& r2, uint32_t& r3, uint32_t a) {
    asm volatile("ldmatrix.sync.aligned.m8n8.x4.shared.b16 {%0,%1,%2,%3}, [%4];"
                 : "=r"(r0), "=r"(r1), "=r"(r2), "=r"(r3) : "r"(a));
}
__device__ __forceinline__ void ldsm_x4t(uint32_t& r0, uint32_t& r1,
                                         uint32_t& r2, uint32_t& r3, uint32_t a) {
    asm volatile("ldmatrix.sync.aligned.m8n8.x4.trans.shared.b16 {%0,%1,%2,%3}, [%4];"
                 : "=r"(r0), "=r"(r1), "=r"(r2), "=r"(r3) : "r"(a));
}
__device__ __forceinline__ void mma16816(float* d, const uint32_t* a, const uint32_t* b) {
    asm volatile(
        "mma.sync.aligned.m16n8k16.row.col.f32.bf16.bf16.f32 "
        "{%0,%1,%2,%3}, {%4,%5,%6,%7}, {%8,%9}, {%0,%1,%2,%3};"
        : "+f"(d[0]), "+f"(d[1]), "+f"(d[2]), "+f"(d[3])
        : "r"(a[0]), "r"(a[1]), "r"(a[2]), "r"(a[3]), "r"(b[0]), "r"(b[1]));
}
__device__ __forceinline__ uint32_t pack_bf16x2(float lo, float hi) {
    uint32_t r;
    asm("cvt.rn.bf16x2.f32 %0, %1, %2;" : "=r"(r) : "f"(hi), "f"(lo));
    return r;
}

// ===========================================================================
// batched fp32 -> bf16 hi/lo split
// ===========================================================================
struct SplitJob { const float4* in; uint2* hi; uint2* lo; int n4; };
struct SplitJobs { SplitJob j[7]; };

__device__ __forceinline__ void do_split(const float4* in, uint2* hi, uint2* lo, int i) {
    float4 v = in[i];
    float f[4] = {v.x, v.y, v.z, v.w};
    uint16_t h[4], l[4];
    #pragma unroll
    for (int j = 0; j < 4; j++) {
        __nv_bfloat16 hb = __float2bfloat16(f[j]);
        __nv_bfloat16 lb = __float2bfloat16(f[j] - __bfloat162float(hb));
        h[j] = __bfloat16_as_ushort(hb);
        l[j] = __bfloat16_as_ushort(lb);
    }
    hi[i] = make_uint2((uint32_t)h[0] | ((uint32_t)h[1] << 16),
                       (uint32_t)h[2] | ((uint32_t)h[3] << 16));
    lo[i] = make_uint2((uint32_t)l[0] | ((uint32_t)l[1] << 16),
                       (uint32_t)l[2] | ((uint32_t)l[3] << 16));
}

__global__ __launch_bounds__(256) void split_batch(SplitJobs jobs) {
    SplitJob jb = jobs.j[blockIdx.y];
    int i = blockIdx.x * 256 + threadIdx.x;
    if (i >= jb.n4) return;
    do_split(jb.in, jb.hi, jb.lo, i);
}

// ===========================================================================
// HMMA bf16-split GEMM core (device function)
// ===========================================================================
#define NTS 16
#define GSTAGE 65536
#define SM_GEMM_BYTES 131072

struct GemmJob {
    const __nv_bfloat16 *ah, *al, *wh, *wl;
    const float* bias;
    __nv_bfloat16 *ch, *cl;
    float scale;
};
struct GemmJobs { GemmJob j[3]; };

__device__ __forceinline__ void gemm_core(
    const __nv_bfloat16* __restrict__ Agh, const __nv_bfloat16* __restrict__ Agl,
    const __nv_bfloat16* __restrict__ Wgh, const __nv_bfloat16* __restrict__ Wgl,
    const float* __restrict__ bias, float* __restrict__ C,
    __nv_bfloat16* __restrict__ Ch, __nv_bfloat16* __restrict__ Cl,
    float scale, int mode, char* smc)
{
    const uint32_t sb = smem_u32(smc);
    const int t = threadIdx.x;
    const int lane = t & 31;
    const int wid = t >> 5;
    const int wm = wid & 1;
    const int wn = wid >> 1;
    const int m0 = blockIdx.y * 128;
    const int n0 = blockIdx.x * 128;

    float acc[4][4][4] = {};

    auto prefetch = [&](int s) {
        const int ksl = s * 64;
        const uint32_t base = sb + (s & 1) * GSTAGE;
        #pragma unroll
        for (int i = 0; i < 4; i++) {
            int idx = t + i * 256;
            int row = idx >> 3, ck = idx & 7;
            uint32_t so = sw128((uint32_t)(row * 128 + ck * 16));
            size_t g = (size_t)(m0 + row) * DD + ksl + ck * 8;
            cp16(base + so, Agh + g);
            cp16(base + 16384 + so, Agl + g);
        }
        #pragma unroll
        for (int i = 0; i < 4; i++) {
            int idx = t + i * 256;
            int kr = idx >> 4, cn = idx & 15;
            uint32_t so = (uint32_t)((cn >> 3) * 8192)
                        + sw128((uint32_t)(kr * 128 + (cn & 7) * 16));
            size_t g = (size_t)(ksl + kr) * DD + n0 + cn * 8;
            cp16(base + 32768 + so, Wgh + g);
            cp16(base + 49152 + so, Wgl + g);
        }
        cp_commit();
    };

    prefetch(0);
    prefetch(1);

    for (int s = 0; s < NTS; s++) {
        if (s < NTS - 1) asm volatile("cp.async.wait_group 1;" ::: "memory");
        else             asm volatile("cp.async.wait_group 0;" ::: "memory");
        __syncthreads();

        const uint32_t aB  = sb + (s & 1) * GSTAGE;
        const uint32_t alB = aB + 16384;
        const uint32_t bhB = aB + 32768;
        const uint32_t blB = aB + 49152;

        const int lg = lane >> 3, l7 = lane & 7;

        #pragma unroll
        for (int ks = 0; ks < 4; ks++) {
            const int kb = ks * 32;
            uint32_t bh[4][2], bl[4][2];
            #pragma unroll
            for (int jj = 0; jj < 2; jj++) {
                int nloc = wn * 32 + jj * 16;
                uint32_t stb = (uint32_t)((nloc >> 6) * 8192);
                int ncol = nloc & 63;
                int krow = ks * 16 + (lg & 1) * 8 + l7;
                uint32_t off = stb + sw128((uint32_t)(krow * 128 + ncol * 2 + (lg >> 1) * 16));
                uint32_t r0, r1, r2, r3;
                ldsm_x4t(r0, r1, r2, r3, bhB + off);
                bh[jj*2+0][0] = r0; bh[jj*2+0][1] = r1;
                bh[jj*2+1][0] = r2; bh[jj*2+1][1] = r3;
                ldsm_x4t(r0, r1, r2, r3, blB + off);
                bl[jj*2+0][0] = r0; bl[jj*2+0][1] = r1;
                bl[jj*2+1][0] = r2; bl[jj*2+1][1] = r3;
            }
            #pragma unroll
            for (int im = 0; im < 4; im++) {
                int arow = wm * 64 + im * 16 + (lg & 1) * 8 + l7;
                uint32_t off = sw128((uint32_t)(arow * 128 + kb + (lg >> 1) * 16));
                uint32_t ah[4], al[4];
                ldsm_x4(ah[0], ah[1], ah[2], ah[3], aB + off);
                ldsm_x4(al[0], al[1], al[2], al[3], alB + off);
                #pragma unroll
                for (int jn = 0; jn < 4; jn++) {
                    mma16816(acc[im][jn], ah, bh[jn]);
                    mma16816(acc[im][jn], ah, bl[jn]);
                    mma16816(acc[im][jn], al, bh[jn]);
                }
            }
        }
        __syncthreads();
        if (s + 2 < NTS) prefetch(s + 2);
    }

    #pragma unroll
    for (int im = 0; im < 4; im++) {
        int r0 = m0 + wm * 64 + im * 16 + (lane >> 2);
        #pragma unroll
        for (int jn = 0; jn < 4; jn++) {
            int col = n0 + wn * 32 + jn * 8 + (lane & 3) * 2;
            float b0 = bias[col], b1 = bias[col + 1];
            float v00 = acc[im][jn][0] + b0, v01 = acc[im][jn][1] + b1;
            float v10 = acc[im][jn][2] + b0, v11 = acc[im][jn][3] + b1;
            if (mode == 0) {
                *(float2*)&C[(size_t)r0 * DD + col] = make_float2(v00, v01);
                *(float2*)&C[(size_t)(r0 + 8) * DD + col] = make_float2(v10, v11);
            } else {
                v00 *= scale; v01 *= scale; v10 *= scale; v11 *= scale;
                int h = col >> 6, dd = col & 63;
                int b_ = r0 >> 11, s0 = r0 & 2047;
                int b2 = (r0 + 8) >> 11, s1 = (r0 + 8) & 2047;
                size_t off0 = ((size_t)(b_ * HH + h) * SS + s0) * DH + dd;
                size_t off1 = ((size_t)(b2 * HH + h) * SS + s1) * DH + dd;
                uint32_t p0 = pack_bf16x2(v00, v01);
                uint32_t p1 = pack_bf16x2(v10, v11);
                *(uint32_t*)&Ch[off0] = p0;
                *(uint32_t*)&Ch[off1] = p1;
                uint32_t q0 = pack_bf16x2(v00 - __uint_as_float(p0 << 16),
                                          v01 - __uint_as_float(p0 & 0xffff0000u));
                uint32_t q1 = pack_bf16x2(v10 - __uint_as_float(p1 << 16),
                                          v11 - __uint_as_float(p1 & 0xffff0000u));
                *(uint32_t*)&Cl[off0] = q0;
                *(uint32_t*)&Cl[off1] = q1;
            }
        }
    }
}

// merged Q/K/V projection (grid.z = 3)
__global__ __launch_bounds__(256, 1) void gemm_hmma_qkv(GemmJobs jobs) {
    extern __shared__ char smc[];
    GemmJob jb = jobs.j[blockIdx.z];
    gemm_core(jb.ah, jb.al, jb.wh, jb.wl, jb.bias, nullptr,
              jb.ch, jb.cl, jb.scale, 2, smc);
}

// output projection (fp32 store)
__global__ __launch_bounds__(256, 1) void gemm_hmma_out(
    const __nv_bfloat16* __restrict__ Agh, const __nv_bfloat16* __restrict__ Agl,
    const __nv_bfloat16* __restrict__ Wgh, const __nv_bfloat16* __restrict__ Wgl,
    const float* __restrict__ bias, float* __restrict__ C)
{
    extern __shared__ char smc[];
    gemm_core(Agh, Agl, Wgh, Wgl, bias, C, nullptr, nullptr, 1.0f, 0, smc);
}

// ===========================================================================
// Fused attention v5 (HMMA).
//  Pass A: single-product QhKh -> Z  (error averages in positive sum: ok)
//  Pass B: 3-product S; p -> attn; O += 3-product P@V (full precision kept)
//  Epilogue: write O as bf16 hi/lo split (merged layout) for the out-proj.
// Q pre-scaled by 0.125*log2(e).
// ===========================================================================
#define FA_STAGE 65536     // Kh 0 / Kl 16K / Vh 32K / Vl 48K
#define FA_SMEM (32768 + 2 * FA_STAGE)

__global__ __launch_bounds__(256, 1) void fused_attn2(
    const __nv_bfloat16* __restrict__ Qh, const __nv_bfloat16* __restrict__ Ql,
    const __nv_bfloat16* __restrict__ Kh, const __nv_bfloat16* __restrict__ Kl,
    const __nv_bfloat16* __restrict__ Vh, const __nv_bfloat16* __restrict__ Vl,
    float* __restrict__ attn,
    __nv_bfloat16* __restrict__ Oh, __nv_bfloat16* __restrict__ Ol)
{
    extern __shared__ char smc[];
    const uint32_t sb = smem_u32(smc);
    const int t = threadIdx.x, lane = t & 31, wid = t >> 5;
    const int m0 = blockIdx.x * 128, bh = blockIdx.y;
    const int mw = wid * 16;
    const size_t gB = (size_t)bh * SS * DH;

    const uint32_t sQh = sb, sQl = sb + 16384;

    const int rA  = mw + (lane & 15);
    const int cA  = (lane & 16);
    const int rBn = (lane & 7) + ((lane & 16) >> 1);
    const int cB  = ((lane & 8) << 1);
    const int rV  = (lane & 7) + (lane & 8);
    const int cV  = (lane >> 4) * 16;

    // Q loads
    #pragma unroll
    for (int i = 0; i < 4; i++) {
        int idx = t + i * 256;
        int row = idx >> 3, ck = idx & 7;
        uint32_t so = sw128((uint32_t)(row * 128 + ck * 16));
        size_t g = gB + (size_t)(m0 + row) * DH + ck * 8;
        cp16(sQh + so, Qh + g);
        cp16(sQl + so, Ql + g);
    }

    auto prefKh = [&](int kt) {
        uint32_t base = sb + 32768 + (uint32_t)(kt & 1) * FA_STAGE;
        #pragma unroll
        for (int i = 0; i < 4; i++) {
            int idx = t + i * 256;
            int row = idx >> 3, ck = idx & 7;
            uint32_t so = sw128((uint32_t)(row * 128 + ck * 16));
            cp16(base + so, Kh + gB + (size_t)(kt * 128 + row) * DH + ck * 8);
        }
        cp_commit();
    };
    auto prefKV = [&](int kt) {
        uint32_t base = sb + 32768 + (uint32_t)(kt & 1) * FA_STAGE;
        #pragma unroll
        for (int i = 0; i < 4; i++) {
            int idx = t + i * 256;
            int row = idx >> 3, ck = idx & 7;
            uint32_t so = sw128((uint32_t)(row * 128 + ck * 16));
            size_t g = gB + (size_t)(kt * 128 + row) * DH + ck * 8;
            cp16(base + so, Kh + g);
            cp16(base + 16384 + so, Kl + g);
            cp16(base + 32768 + so, Vh + g);
            cp16(base + 49152 + so, Vl + g);
        }
        cp_commit();
    };

    auto computeS1 = [&](uint32_t kb, float (*acc)[4]) {
        #pragma unroll
        for (int kg = 0; kg < 4; kg++) {
            uint32_t offA = sw128((uint32_t)(rA * 128 + kg * 32 + cA));
            uint32_t ah[4];
            ldsm_x4(ah[0], ah[1], ah[2], ah[3], sQh + offA);
            #pragma unroll
            for (int j = 0; j < 8; j++) {
                uint32_t offB = sw128((uint32_t)((j * 16 + rBn) * 128 + kg * 32 + cB));
                uint32_t b0, b1, b2, b3;
                ldsm_x4(b0, b1, b2, b3, kb + offB);
                uint32_t bh0[2] = {b0, b1}, bh1[2] = {b2, b3};
                mma16816(acc[2*j],   ah, bh0);
                mma16816(acc[2*j+1], ah, bh1);
            }
        }
    };
    auto computeS3 = [&](uint32_t kb, float (*acc)[4]) {
        #pragma unroll
        for (int kg = 0; kg < 4; kg++) {
            uint32_t offA = sw128((uint32_t)(rA * 128 + kg * 32 + cA));
            uint32_t ah[4], al[4];
            ldsm_x4(ah[0], ah[1], ah[2], ah[3], sQh + offA);
            ldsm_x4(al[0], al[1], al[2], al[3], sQl + offA);
            #pragma unroll
            for (int j = 0; j < 8; j++) {
                uint32_t offB = sw128((uint32_t)((j * 16 + rBn) * 128 + kg * 32 + cB));
                uint32_t b0, b1, b2, b3, c0, c1, c2, c3;
                ldsm_x4(b0, b1, b2, b3, kb + offB);
                ldsm_x4(c0, c1, c2, c3, kb + 16384 + offB);
                uint32_t bh0[2] = {b0, b1}, bh1[2] = {b2, b3};
                uint32_t bl0[2] = {c0, c1}, bl1[2] = {c2, c3};
                mma16816(acc[2*j],   ah, bh0);
                mma16816(acc[2*j],   al, bh0);
                mma16816(acc[2*j],   ah, bl0);
                mma16816(acc[2*j+1], ah, bh1);
                mma16816(acc[2*j+1], al, bh1);
                mma16816(acc[2*j+1], ah, bl1);
            }
        }
    };

    prefKh(0);
    prefKh(1);

    // ------------------- Pass A -------------------
    float sum0 = 0.f, sum1 = 0.f;
    for (int kt = 0; kt < 16; kt++) {
        if (kt < 15) asm volatile("cp.async.wait_group 1;" ::: "memory");
        else         asm volatile("cp.async.wait_group 0;" ::: "memory");
        __syncthreads();
        uint32_t kb = sb + 32768 + (uint32_t)(kt & 1) * FA_STAGE;

        float acc[16][4] = {};
        computeS1(kb, acc);

        #pragma unroll
        for (int nt = 0; nt < 16; nt++) {
            sum0 += fast_exp2(acc[nt][0]) + fast_exp2(acc[nt][1]);
            sum1 += fast_exp2(acc[nt][2]) + fast_exp2(acc[nt][3]);
        }
        __syncthreads();
        if (kt + 2 < 16) prefKh(kt + 2);
    }

    sum0 += __shfl_xor_sync(0xffffffffu, sum0, 1);
    sum0 += __shfl_xor_sync(0xffffffffu, sum0, 2);
    sum1 += __shfl_xor_sync(0xffffffffu, sum1, 1);
    sum1 += __shfl_xor_sync(0xffffffffu, sum1, 2);
    const float invZ0 = 1.0f / sum0;
    const float invZ1 = 1.0f / sum1;

    __syncthreads();
    prefKV(0);
    prefKV(1);

    // ------------------- Pass B -------------------
    float o[8][4] = {};
    const size_t arow0 = (size_t)bh * SS + m0 + mw + (lane >> 2);
    const size_t arow8 = arow0 + 8;

    for (int kt = 0; kt < 16; kt++) {
        if (kt < 15) asm volatile("cp.async.wait_group 1;" ::: "memory");
        else         asm volatile("cp.async.wait_group 0;" ::: "memory");
        __syncthreads();
        uint32_t kb = sb + 32768 + (uint32_t)(kt & 1) * FA_STAGE;

        float acc[16][4] = {};
        computeS3(kb, acc);

        #pragma unroll
        for (int nt = 0; nt < 16; nt++) {
            float p0 = fast_exp2(acc[nt][0]) * invZ0;
            float p1 = fast_exp2(acc[nt][1]) * invZ0;
            float p2 = fast_exp2(acc[nt][2]) * invZ1;
            float p3 = fast_exp2(acc[nt][3]) * invZ1;
            acc[nt][0] = p0; acc[nt][1] = p1; acc[nt][2] = p2; acc[nt][3] = p3;
            int col = kt * 128 + nt * 8 + (lane & 3) * 2;
            *(float2*)&attn[arow0 * SS + col] = make_float2(p0, p1);
            *(float2*)&attn[arow8 * SS + col] = make_float2(p2, p3);
        }

        #pragma unroll
        for (int kg = 0; kg < 8; kg++) {
            uint32_t ph[4], pl[4];
            #pragma unroll
            for (int half = 0; half < 2; half++) {
                float* a4 = acc[2*kg + half];
                uint32_t h0 = pack_bf16x2(a4[0], a4[1]);
                uint32_t h1 = pack_bf16x2(a4[2], a4[3]);
                ph[half*2 + 0] = h0;
                ph[half*2 + 1] = h1;
                pl[half*2 + 0] = pack_bf16x2(a4[0] - __uint_as_float(h0 << 16),
                                             a4[1] - __uint_as_float(h0 & 0xffff0000u));
                pl[half*2 + 1] = pack_bf16x2(a4[2] - __uint_as_float(h1 << 16),
                                             a4[3] - __uint_as_float(h1 & 0xffff0000u));
            }
            #pragma unroll
            for (int j = 0; j < 4; j++) {
                uint32_t offV = sw128((uint32_t)((kg * 16 + rV) * 128 + j * 32 + cV));
                uint32_t v0, v1, v2, v3, w0, w1, w2, w3;
                ldsm_x4t(v0, v1, v2, v3, kb + 32768 + offV);
                ldsm_x4t(w0, w1, w2, w3, kb + 49152 + offV);
                uint32_t vh0[2] = {v0, v1}, vh1[2] = {v2, v3};
                uint32_t vl0[2] = {w0, w1}, vl1[2] = {w2, w3};
                mma16816(o[2*j],   ph, vh0);
                mma16816(o[2*j],   pl, vh0);
                mma16816(o[2*j],   ph, vl0);
                mma16816(o[2*j+1], ph, vh1);
                mma16816(o[2*j+1], pl, vh1);
                mma16816(o[2*j+1], ph, vl1);
            }
        }
        __syncthreads();
        if (kt + 2 < 16) prefKV(kt + 2);
    }

    // ---- epilogue: store O as bf16 hi/lo split, merged layout ----
    const int b = bh >> 4, h = bh & 15;
    const size_t mrow0 = (size_t)(b * SS + m0 + mw + (lane >> 2));
    #pragma unroll
    for (int nt = 0; nt < 8; nt++) {
        int col = h * 64 + nt * 8 + (lane & 3) * 2;
        size_t off0 = mrow0 * DD + col;
        size_t off1 = (mrow0 + 8) * DD + col;
        uint32_t p0 = pack_bf16x2(o[nt][0], o[nt][1]);
        uint32_t p1 = pack_bf16x2(o[nt][2], o[nt][3]);
        *(uint32_t*)&Oh[off0] = p0;
        *(uint32_t*)&Oh[off1] = p1;
        uint32_t q0 = pack_bf16x2(o[nt][0] - __uint_as_float(p0 << 16),
                                  o[nt][1] - __uint_as_float(p0 & 0xffff0000u));
        uint32_t q1 = pack_bf16x2(o[nt][2] - __uint_as_float(p1 << 16),
                                  o[nt][3] - __uint_as_float(p1 & 0xffff0000u));
        *(uint32_t*)&Ol[off0] = q0;
        *(uint32_t*)&Ol[off1] = q1;
    }
}

// ===========================================================================
extern "C" void kernel_launch(void* const* d_in, const int* in_sizes, int n_in,
                              void* d_out, int out_size)
{
    const float* q  = (const float*)d_in[0];
    const float* k  = (const float*)d_in[1];
    const float* v  = (const float*)d_in[2];
    const float* Wq = (const float*)d_in[4];
    const float* bq = (const float*)d_in[5];
    const float* Wk = (const float*)d_in[6];
    const float* bk = (const float*)d_in[7];
    const float* Wv = (const float*)d_in[8];
    const float* bv = (const float*)d_in[9];
    const float* Wo = (const float*)d_in[10];
    const float* bo = (const float*)d_in[11];

    float* out_ptr  = (float*)d_out;
    float* attn_ptr = (float*)d_out + OUT_ELEMS;

    __nv_bfloat16 *gAh, *gAl;
    __nv_bfloat16 *gSqh, *gSql, *gSkh, *gSkl, *gSvh, *gSvl;
    __nv_bfloat16 *gW1h, *gW1l, *gW2h, *gW2l, *gW3h, *gW3l, *gW4h, *gW4l;
    __nv_bfloat16 *gQh, *gQl, *gKh, *gKl, *gVh, *gVl;
    cudaGetSymbolAddress((void**)&gAh, g_Ah);
    cudaGetSymbolAddress((void**)&gAl, g_Al);
    cudaGetSymbolAddress((void**)&gSqh, g_Sqh); cudaGetSymbolAddress((void**)&gSql, g_Sql);
    cudaGetSymbolAddress((void**)&gSkh, g_Skh); cudaGetSymbolAddress((void**)&gSkl, g_Skl);
    cudaGetSymbolAddress((void**)&gSvh, g_Svh); cudaGetSymbolAddress((void**)&gSvl, g_Svl);
    cudaGetSymbolAddress((void**)&gW1h, g_W1h); cudaGetSymbolAddress((void**)&gW1l, g_W1l);
    cudaGetSymbolAddress((void**)&gW2h, g_W2h); cudaGetSymbolAddress((void**)&gW2l, g_W2l);
    cudaGetSymbolAddress((void**)&gW3h, g_W3h); cudaGetSymbolAddress((void**)&gW3l, g_W3l);
    cudaGetSymbolAddress((void**)&gW4h, g_W4h); cudaGetSymbolAddress((void**)&gW4l, g_W4l);
    cudaGetSymbolAddress((void**)&gQh, g_Qh); cudaGetSymbolAddress((void**)&gQl, g_Ql);
    cudaGetSymbolAddress((void**)&gKh, g_Kh); cudaGetSymbolAddress((void**)&gKl, g_Kl);
    cudaGetSymbolAddress((void**)&gVh, g_Vh); cudaGetSymbolAddress((void**)&gVl, g_Vl);

    cudaFuncSetAttribute(gemm_hmma_qkv, cudaFuncAttributeMaxDynamicSharedMemorySize,
                         SM_GEMM_BYTES);
    cudaFuncSetAttribute(gemm_hmma_out, cudaFuncAttributeMaxDynamicSharedMemorySize,
                         SM_GEMM_BYTES);
    cudaFuncSetAttribute(fused_attn2, cudaFuncAttributeMaxDynamicSharedMemorySize,
                         FA_SMEM);

    const int NA4 = (int)(OUT_ELEMS / 4);
    const int NW4 = DD * DD / 4;

    // Batched splits: q, k, v, Wq, Wk, Wv, Wo
    SplitJobs jobs;
    jobs.j[0] = { (const float4*)q,  (uint2*)gSqh, (uint2*)gSql, NA4 };
    jobs.j[1] = { (const float4*)k,  (uint2*)gSkh, (uint2*)gSkl, NA4 };
    jobs.j[2] = { (const float4*)v,  (uint2*)gSvh, (uint2*)gSvl, NA4 };
    jobs.j[3] = { (const float4*)Wq, (uint2*)gW1h, (uint2*)gW1l, NW4 };
    jobs.j[4] = { (const float4*)Wk, (uint2*)gW2h, (uint2*)gW2l, NW4 };
    jobs.j[5] = { (const float4*)Wv, (uint2*)gW3h, (uint2*)gW3l, NW4 };
    jobs.j[6] = { (const float4*)Wo, (uint2*)gW4h, (uint2*)gW4l, NW4 };
    split_batch<<<dim3((NA4 + 255) / 256, 7), 256>>>(jobs);

    // Merged Q/K/V projections (Q scaled by 0.125*log2e)
    const float QSCALE = 0.125f * 1.4426950408889634f;
    GemmJobs gj;
    gj.j[0] = { gSqh, gSql, gW1h, gW1l, bq, gQh, gQl, QSCALE };
    gj.j[1] = { gSkh, gSkl, gW2h, gW2l, bk, gKh, gKl, 1.0f };
    gj.j[2] = { gSvh, gSvl, gW3h, gW3l, bv, gVh, gVl, 1.0f };
    dim3 gp3(DD / 128, NROW / 128, 3);
    gemm_hmma_qkv<<<gp3, 256, SM_GEMM_BYTES>>>(gj);

    // Fused attention (writes bf16-split O directly)
    dim3 gf(SS / 128, BB * HH);
    fused_attn2<<<gf, 256, FA_SMEM>>>(gQh, gQl, gKh, gKl, gVh, gVl, attn_ptr, gAh, gAl);

    // Output projection
    dim3 gp(DD / 128, NROW / 128);
    gemm_hmma_out<<<gp, 256, SM_GEMM_BYTES>>>(gAh, gAl, gW4h, gW4l, bo, out_ptr);
}